// round 1
// baseline (speedup 1.0000x reference)
#include <cuda_runtime.h>
#include <math.h>

#define NN 50000
#define EE 400000
#define GG 2000
#define HH 128
#define LL 5
#define NPGC 25

// ---------------- scratch (device globals; no allocation allowed) ----------------
__device__ float g_HA[NN * 640];          // [h | agg] per node
__device__ float g_AB[NN * 256];          // [A=h@Wsrc | B=h@Wdst]
__device__ float g_Y[NN * 384];           // post-GEMM output (3 blocks of 128)
__device__ float g_hbuf0[NN * HH];
__device__ float g_hbuf1[NN * HH];
__device__ float g_Wsd[2][LL * 128 * 256];   // repacked [K=128, N=256]
__device__ float g_Wbig[2][LL * 640 * 384];  // repacked [K=640, N=384]
__device__ float g_combo[2][125 * HH];       // 125 distinct edge embeddings
__device__ float g_Ctab[125 * HH];           // per-layer edge-term table (+bias)
__device__ int   g_deg[NN];
__device__ int   g_rowptr[NN + 1];
__device__ int   g_cursor[NN];
__device__ int   g_elist[EE];                // packed: src | (cid<<16)
__device__ float g_amp[NN];
__device__ float g_att[NN];
__device__ float g_R3[GG * 384];
__device__ float g_XB[GG * 640];             // [r2(384) | latent3d(256)]
__device__ float g_H1[GG * HH];

// ---------------- small kernels ----------------
__global__ void count_kernel(const int* __restrict__ dst) {
    int e = blockIdx.x * blockDim.x + threadIdx.x;
    if (e < EE) atomicAdd(&g_deg[dst[e]], 1);
}

__global__ void scan_kernel() {
    __shared__ int part[1024];
    int t = threadIdx.x;
    const int CH = (NN + 1023) / 1024;
    int base = t * CH;
    int s = 0;
    for (int i = 0; i < CH; i++) {
        int idx = base + i;
        if (idx < NN) s += g_deg[idx];
    }
    part[t] = s;
    __syncthreads();
    for (int off = 1; off < 1024; off <<= 1) {
        int v = (t >= off) ? part[t - off] : 0;
        __syncthreads();
        part[t] += v;
        __syncthreads();
    }
    int run = (t == 0) ? 0 : part[t - 1];
    for (int i = 0; i < CH; i++) {
        int idx = base + i;
        if (idx < NN) { g_rowptr[idx] = run; run += g_deg[idx]; }
    }
    if (t == 1023) g_rowptr[NN] = part[1023];
}

__global__ void scalars_kernel() {
    int n = blockIdx.x * blockDim.x + threadIdx.x;
    if (n >= NN) return;
    int d = g_deg[n];
    float ld = logf((float)d + 1.0f);
    g_amp[n] = ld;                       // log_deg / D_LOG, D_LOG=1
    g_att[n] = (d > 0) ? (1.0f / ld) : 0.0f;
}

__global__ void fill_kernel(const int* __restrict__ src, const int* __restrict__ dst,
                            const int* __restrict__ ef) {
    int e = blockIdx.x * blockDim.x + threadIdx.x;
    if (e >= EE) return;
    int d = dst[e];
    int pos = g_rowptr[d] + atomicAdd(&g_cursor[d], 1);
    int c = ef[e * 3 + 0] + 5 * ef[e * 3 + 1] + 25 * ef[e * 3 + 2];
    g_elist[pos] = src[e] | (c << 16);
}

__global__ void combo_kernel(const float* __restrict__ bemb, float* __restrict__ combo) {
    int c = blockIdx.x;      // 0..124
    int t = threadIdx.x;     // 0..127
    int f0 = c % 5, f1 = (c / 5) % 5, f2 = c / 25;
    combo[c * HH + t] = bemb[f0 * HH + t] + bemb[(5 + f1) * HH + t] + bemb[(10 + f2) * HH + t];
}

__global__ void embed_kernel(const float* __restrict__ aemb, const int* __restrict__ nf,
                             float* __restrict__ h0) {
    int n = blockIdx.x;
    int t = threadIdx.x;
    float acc = 0.0f;
#pragma unroll
    for (int j = 0; j < 9; j++) {
        int idx = nf[n * 9 + j] + j * 16;
        acc += aemb[idx * HH + t];
    }
    h0[n * HH + t] = acc;
}

// Ctab[c] = combo[c] @ Wedge + b_pre  (tiny GEMM, 125x128x128)
__global__ void ctab_kernel(const float* __restrict__ combo, const float* __restrict__ We,
                            const float* __restrict__ bias) {
    __shared__ float s[HH];
    int c = blockIdx.x, t = threadIdx.x;
    s[t] = combo[c * HH + t];
    __syncthreads();
    float acc = bias[t];
#pragma unroll 8
    for (int k = 0; k < HH; k++) acc += s[k] * We[k * HH + t];
    g_Ctab[c * HH + t] = acc;
}

__global__ void repack_wsd_kernel(const float* __restrict__ wpre, float* __restrict__ out) {
    int idx = blockIdx.x * blockDim.x + threadIdx.x;
    if (idx >= LL * 128 * 256) return;
    int l = idx / (128 * 256);
    int rem = idx % (128 * 256);
    int k = rem / 256;
    int c = rem % 256;
    int p = c >> 7, j = c & 127;
    out[idx] = wpre[l * 49152 + (p * 128 + k) * 128 + j];
}

__global__ void repack_wbig_kernel(const float* __restrict__ wpost, float* __restrict__ out) {
    int idx = blockIdx.x * blockDim.x + threadIdx.x;
    if (idx >= LL * 640 * 384) return;
    int l = idx / (640 * 384);
    int rem = idx % (640 * 384);
    int r = rem / 384;
    int c = rem % 384;
    int p = c >> 7, j = c & 127;
    float v;
    if (r < 128) {
        v = (p == 0) ? wpost[l * 212992 + r * 128 + j] : 0.0f;
    } else {
        int a = r - 128;
        v = wpost[l * 212992 + (128 + p * 512 + a) * 128 + j];
    }
    out[idx] = v;
}

// ---------------- edge aggregation (warp per node) ----------------
__global__ void aggregate_kernel(const float* __restrict__ hcur) {
    int node = blockIdx.x * 8 + (threadIdx.x >> 5);
    if (node >= NN) return;
    int lane = threadIdx.x & 31;
    int h4 = lane * 4;
    float4 b4 = *(const float4*)&g_AB[node * 256 + 128 + h4];
    float sx = 0, sy = 0, sz = 0, sw = 0;
    float qx = 0, qy = 0, qz = 0, qw = 0;
    float mxx = -1e30f, mxy = -1e30f, mxz = -1e30f, mxw = -1e30f;
    float mnx = 1e30f, mny = 1e30f, mnz = 1e30f, mnw = 1e30f;
    int start = g_rowptr[node], end = g_rowptr[node + 1];
    for (int i = start; i < end; i++) {
        int packed = g_elist[i];
        int s = packed & 0xFFFF;
        int c = packed >> 16;
        float4 a4 = *(const float4*)&g_AB[s * 256 + h4];
        float4 c4 = *(const float4*)&g_Ctab[c * HH + h4];
        float zx = a4.x + b4.x + c4.x;
        float zy = a4.y + b4.y + c4.y;
        float zz = a4.z + b4.z + c4.z;
        float zw = a4.w + b4.w + c4.w;
        sx += zx; sy += zy; sz += zz; sw += zw;
        qx += zx * zx; qy += zy * zy; qz += zz * zz; qw += zw * zw;
        mxx = fmaxf(mxx, zx); mxy = fmaxf(mxy, zy); mxz = fmaxf(mxz, zz); mxw = fmaxf(mxw, zw);
        mnx = fminf(mnx, zx); mny = fminf(mny, zy); mnz = fminf(mnz, zz); mnw = fminf(mnw, zw);
    }
    float* out = &g_HA[node * 640];
    *(float4*)&out[h4] = *(const float4*)&hcur[node * HH + h4];
    int deg = end - start;
    if (deg == 0) {
        float4 z4 = make_float4(0, 0, 0, 0);
        *(float4*)&out[128 + h4] = z4;
        *(float4*)&out[256 + h4] = z4;
        *(float4*)&out[384 + h4] = z4;
        *(float4*)&out[512 + h4] = z4;
    } else {
        float inv = 1.0f / (float)deg;
        float mex = sx * inv, mey = sy * inv, mez = sz * inv, mew = sw * inv;
        float vx = fmaxf(qx * inv - mex * mex, 0.0f);
        float vy = fmaxf(qy * inv - mey * mey, 0.0f);
        float vz = fmaxf(qz * inv - mez * mez, 0.0f);
        float vw = fmaxf(qw * inv - mew * mew, 0.0f);
        *(float4*)&out[128 + h4] = make_float4(mex, mey, mez, mew);
        *(float4*)&out[256 + h4] = make_float4(mxx, mxy, mxz, mxw);
        *(float4*)&out[384 + h4] = make_float4(mnx, mny, mnz, mnw);
        *(float4*)&out[512 + h4] = make_float4(sqrtf(vx + 1e-5f), sqrtf(vy + 1e-5f),
                                               sqrtf(vz + 1e-5f), sqrtf(vw + 1e-5f));
    }
}

__global__ void combine_kernel(const float* __restrict__ hcur, const float* __restrict__ bpost,
                               float* __restrict__ hnext) {
    int idx = blockIdx.x * blockDim.x + threadIdx.x;
    if (idx >= NN * HH) return;
    int n = idx >> 7;
    int h = idx & 127;
    const float* y = &g_Y[n * 384];
    float v = y[h] + g_amp[n] * y[128 + h] + g_att[n] * y[256 + h] + bpost[h] + hcur[idx];
    hnext[idx] = v;
}

__global__ void readout_kernel(const float* __restrict__ h, float* __restrict__ out, int ldo) {
    int g = blockIdx.x;
    int t = threadIdx.x;
    float mn = 1e30f, mx = -1e30f, s = 0.0f;
#pragma unroll
    for (int i = 0; i < NPGC; i++) {
        float v = h[(g * NPGC + i) * HH + t];
        mn = fminf(mn, v);
        mx = fmaxf(mx, v);
        s += v;
    }
    out[g * ldo + t] = mn;
    out[g * ldo + 128 + t] = mx;
    out[g * ldo + 256 + t] = s * (1.0f / (float)NPGC);
}

// ---------------- generic fp32 tiled GEMM: C[M,N] = A[M,K]@B[K,N] (+bias)(+relu) ----------------
// BM=BN=64, BK=16, 256 threads, 4x4 per thread.
__global__ void gemm_kernel(const float* __restrict__ A, const float* __restrict__ B,
                            float* __restrict__ C, const float* __restrict__ bias,
                            int M, int N, int K, int ldc, int relu) {
    __shared__ float As[16][64];
    __shared__ float Bs[16][64];
    int tid = threadIdx.x;
    int tx = tid & 15, ty = tid >> 4;
    int row0 = blockIdx.y * 64, col0 = blockIdx.x * 64;
    float acc[4][4];
#pragma unroll
    for (int i = 0; i < 4; i++)
#pragma unroll
        for (int j = 0; j < 4; j++) acc[i][j] = 0.0f;

    int ar = tid >> 2, ac = (tid & 3) * 4;     // A tile: 64 rows x 16 cols
    int br = tid >> 4, bc = (tid & 15) * 4;    // B tile: 16 rows x 64 cols
    int arow = row0 + ar;

    for (int k0 = 0; k0 < K; k0 += 16) {
        float4 a4 = make_float4(0, 0, 0, 0);
        if (arow < M) a4 = *(const float4*)&A[arow * K + k0 + ac];
        As[ac + 0][ar] = a4.x;
        As[ac + 1][ar] = a4.y;
        As[ac + 2][ar] = a4.z;
        As[ac + 3][ar] = a4.w;
        *(float4*)&Bs[br][bc] = *(const float4*)&B[(k0 + br) * N + col0 + bc];
        __syncthreads();
#pragma unroll
        for (int k = 0; k < 16; k++) {
            float4 av = *(const float4*)&As[k][ty * 4];
            float4 bv = *(const float4*)&Bs[k][tx * 4];
            acc[0][0] += av.x * bv.x; acc[0][1] += av.x * bv.y; acc[0][2] += av.x * bv.z; acc[0][3] += av.x * bv.w;
            acc[1][0] += av.y * bv.x; acc[1][1] += av.y * bv.y; acc[1][2] += av.y * bv.z; acc[1][3] += av.y * bv.w;
            acc[2][0] += av.z * bv.x; acc[2][1] += av.z * bv.y; acc[2][2] += av.z * bv.z; acc[2][3] += av.z * bv.w;
            acc[3][0] += av.w * bv.x; acc[3][1] += av.w * bv.y; acc[3][2] += av.w * bv.z; acc[3][3] += av.w * bv.w;
        }
        __syncthreads();
    }
#pragma unroll
    for (int i = 0; i < 4; i++) {
        int r = row0 + ty * 4 + i;
        if (r >= M) continue;
#pragma unroll
        for (int j = 0; j < 4; j++) {
            int col = col0 + tx * 4 + j;
            float v = acc[i][j];
            if (bias) v += bias[col];
            if (relu) v = fmaxf(v, 0.0f);
            C[r * ldc + col] = v;
        }
    }
}

// ---------------- host ----------------
static void launch_gemm(const float* A, const float* B, float* C, const float* bias,
                        int M, int N, int K, int ldc, int relu) {
    dim3 grid(N / 64, (M + 63) / 64);
    gemm_kernel<<<grid, 256>>>(A, B, C, bias, M, N, K, ldc, relu);
}

extern "C" void kernel_launch(void* const* d_in, const int* in_sizes, int n_in,
                              void* d_out, int out_size) {
    // ---- identify inputs by element count (duplicates resolved in order) ----
    const int *node_feat = 0, *edge_feat = 0, *srcp = 0, *dstp = 0;
    const float *aemb_f = 0, *bemb_f = 0, *wpre_f = 0, *bpre_f = 0, *wpost_f = 0, *bpost_f = 0;
    const float *wout3 = 0, *bout3 = 0;
    const float *aemb = 0, *bemb = 0, *wpre = 0, *bpre = 0, *wpost = 0, *bpost = 0;
    const float *w1 = 0, *b1 = 0, *w2 = 0, *b2 = 0;
    int c400k = 0, c18432 = 0, c1920 = 0, c245760 = 0, c640 = 0, c1064960 = 0, c128 = 0;
    for (int i = 0; i < n_in; i++) {
        int sz = in_sizes[i];
        void* p = d_in[i];
        switch (sz) {
            case 450000: node_feat = (const int*)p; break;
            case 1200000: edge_feat = (const int*)p; break;
            case 400000: if (c400k++ == 0) srcp = (const int*)p; else dstp = (const int*)p; break;
            case 50000: /* graph_id: implicit n/25 */ break;
            case 18432: if (c18432++ == 0) aemb_f = (const float*)p; else aemb = (const float*)p; break;
            case 1920: if (c1920++ == 0) bemb_f = (const float*)p; else bemb = (const float*)p; break;
            case 245760: if (c245760++ == 0) wpre_f = (const float*)p; else wpre = (const float*)p; break;
            case 640: {
                int k = c640++;
                if (k == 0) bpre_f = (const float*)p;
                else if (k == 1) bpost_f = (const float*)p;
                else if (k == 2) bpre = (const float*)p;
                else bpost = (const float*)p;
            } break;
            case 1064960: if (c1064960++ == 0) wpost_f = (const float*)p; else wpost = (const float*)p; break;
            case 98304: wout3 = (const float*)p; break;
            case 256: bout3 = (const float*)p; break;
            case 81920: w1 = (const float*)p; break;
            case 128: if (c128++ == 0) b1 = (const float*)p; else b2 = (const float*)p; break;
            case 16384: w2 = (const float*)p; break;
            default: break;
        }
    }

    // ---- scratch addresses ----
    float *HA, *AB, *Y, *h0b, *h1b, *Wsd, *Wbig, *combo, *Ctab, *R3, *XB, *H1;
    int *deg, *cursor;
    cudaGetSymbolAddress((void**)&HA, g_HA);
    cudaGetSymbolAddress((void**)&AB, g_AB);
    cudaGetSymbolAddress((void**)&Y, g_Y);
    cudaGetSymbolAddress((void**)&h0b, g_hbuf0);
    cudaGetSymbolAddress((void**)&h1b, g_hbuf1);
    cudaGetSymbolAddress((void**)&Wsd, g_Wsd);
    cudaGetSymbolAddress((void**)&Wbig, g_Wbig);
    cudaGetSymbolAddress((void**)&combo, g_combo);
    cudaGetSymbolAddress((void**)&Ctab, g_Ctab);
    cudaGetSymbolAddress((void**)&R3, g_R3);
    cudaGetSymbolAddress((void**)&XB, g_XB);
    cudaGetSymbolAddress((void**)&H1, g_H1);
    cudaGetSymbolAddress((void**)&deg, g_deg);
    cudaGetSymbolAddress((void**)&cursor, g_cursor);

    // ---- graph preprocessing ----
    cudaMemsetAsync(deg, 0, NN * sizeof(int));
    cudaMemsetAsync(cursor, 0, NN * sizeof(int));
    count_kernel<<<(EE + 255) / 256, 256>>>(dstp);
    scan_kernel<<<1, 1024>>>();
    scalars_kernel<<<(NN + 255) / 256, 256>>>();
    fill_kernel<<<(EE + 255) / 256, 256>>>(srcp, dstp, edge_feat);

    // ---- weight repacks + combo tables ----
    const float* bembs[2] = { bemb_f, bemb };
    const float* aembs[2] = { aemb_f, aemb };
    const float* wpres[2] = { wpre_f, wpre };
    const float* bpres[2] = { bpre_f, bpre };
    const float* wposts[2] = { wpost_f, wpost };
    const float* bposts[2] = { bpost_f, bpost };
    for (int br = 0; br < 2; br++) {
        combo_kernel<<<125, 128>>>(bembs[br], combo + br * 125 * HH);
        repack_wsd_kernel<<<(LL * 128 * 256 + 255) / 256, 256>>>(wpres[br], Wsd + br * LL * 128 * 256);
        repack_wbig_kernel<<<(LL * 640 * 384 + 255) / 256, 256>>>(wposts[br], Wbig + br * LL * 640 * 384);
    }

    // ---- two GNN branches: br=0 frozen -> latent3d, br=1 trainable -> r2 ----
    for (int br = 0; br < 2; br++) {
        embed_kernel<<<NN, 128>>>(aembs[br], node_feat, h0b);
        float* hcur = h0b;
        float* hnext = h1b;
        for (int l = 0; l < LL; l++) {
            ctab_kernel<<<125, 128>>>(combo + br * 125 * HH,
                                      wpres[br] + l * 49152 + 256 * 128,
                                      bpres[br] + l * 128);
            launch_gemm(hcur, Wsd + br * LL * 128 * 256 + l * 128 * 256, AB, 0,
                        NN, 256, 128, 256, 0);
            aggregate_kernel<<<(NN + 7) / 8, 256>>>(hcur);
            launch_gemm(HA, Wbig + br * LL * 640 * 384 + l * 640 * 384, Y, 0,
                        NN, 384, 640, 384, 0);
            combine_kernel<<<(NN * HH + 255) / 256, 256>>>(hcur, bposts[br] + l * 128, hnext);
            float* tmp = hcur; hcur = hnext; hnext = tmp;
        }
        if (br == 0) {
            readout_kernel<<<GG, 128>>>(hcur, R3, 384);
            launch_gemm(R3, wout3, XB + 384, bout3, GG, 256, 384, 640, 0);  // latent3d
        } else {
            readout_kernel<<<GG, 128>>>(hcur, XB, 640);  // r2 into XB[:,0:384]
        }
    }

    // ---- head ----
    launch_gemm(XB, w1, H1, b1, GG, 128, 640, 128, 1);
    launch_gemm(H1, w2, (float*)d_out, b2, GG, 128, 128, 128, 0);
    (void)out_size;
}

// round 3
// speedup vs baseline: 1.6927x; 1.6927x over previous
#include <cuda_runtime.h>
#include <cuda_bf16.h>
#include <cstdint>
#include <math.h>

#define NN 50000
#define EE 400000
#define GG 2000
#define HH 128
#define LL 5
#define NPGC 25

// ================= scratch (device globals) =================
__device__ __nv_bfloat16 g_HAhi[(size_t)NN * 640];
__device__ __nv_bfloat16 g_HAlo[(size_t)NN * 640];
__device__ __nv_bfloat16 g_hhi[NN * HH];
__device__ __nv_bfloat16 g_hlo[NN * HH];
__device__ float g_AB[(size_t)NN * 256];
__device__ float g_Y[(size_t)NN * 384];
__device__ float g_hbuf0[NN * HH];
__device__ float g_hbuf1[NN * HH];
__device__ __nv_bfloat16 g_WsdHi[2][LL * 256 * 128];
__device__ __nv_bfloat16 g_WsdLo[2][LL * 256 * 128];
__device__ __nv_bfloat16 g_WbigHi[2][LL * 384 * 640];
__device__ __nv_bfloat16 g_WbigLo[2][LL * 384 * 640];
__device__ float g_combo[2][125 * HH];
__device__ float g_Ctab[125 * HH];
__device__ int   g_deg[NN];
__device__ int   g_rowptr[NN + 1];
__device__ int   g_cursor[NN];
__device__ int   g_elist[EE];
__device__ float g_amp[NN];
__device__ float g_att[NN];
__device__ float g_R3[GG * 384];
__device__ float g_XB[GG * 640];
__device__ float g_H1[GG * HH];

__device__ __forceinline__ void split_bf(float x, __nv_bfloat16& h, __nv_bfloat16& l) {
    h = __float2bfloat16_rn(x);
    l = __float2bfloat16_rn(x - __bfloat162float(h));
}

// ================= graph preprocessing =================
__global__ void count_kernel(const int* __restrict__ dst) {
    int e = blockIdx.x * blockDim.x + threadIdx.x;
    if (e < EE) atomicAdd(&g_deg[dst[e]], 1);
}

__global__ void scan_kernel() {
    __shared__ int part[1024];
    int t = threadIdx.x;
    const int CH = (NN + 1023) / 1024;
    int base = t * CH;
    int s = 0;
    for (int i = 0; i < CH; i++) { int idx = base + i; if (idx < NN) s += g_deg[idx]; }
    part[t] = s;
    __syncthreads();
    for (int off = 1; off < 1024; off <<= 1) {
        int v = (t >= off) ? part[t - off] : 0;
        __syncthreads();
        part[t] += v;
        __syncthreads();
    }
    int run = (t == 0) ? 0 : part[t - 1];
    for (int i = 0; i < CH; i++) {
        int idx = base + i;
        if (idx < NN) { g_rowptr[idx] = run; run += g_deg[idx]; }
    }
    if (t == 1023) g_rowptr[NN] = part[1023];
}

__global__ void scalars_kernel() {
    int n = blockIdx.x * blockDim.x + threadIdx.x;
    if (n >= NN) return;
    int d = g_deg[n];
    float ld = logf((float)d + 1.0f);
    g_amp[n] = ld;
    g_att[n] = (d > 0) ? (1.0f / ld) : 0.0f;
}

__global__ void fill_kernel(const int* __restrict__ src, const int* __restrict__ dst,
                            const int* __restrict__ ef) {
    int e = blockIdx.x * blockDim.x + threadIdx.x;
    if (e >= EE) return;
    int d = dst[e];
    int pos = g_rowptr[d] + atomicAdd(&g_cursor[d], 1);
    int c = ef[e * 3 + 0] + 5 * ef[e * 3 + 1] + 25 * ef[e * 3 + 2];
    g_elist[pos] = src[e] | (c << 16);
}

__global__ void combo_kernel(const float* __restrict__ bemb, float* __restrict__ combo) {
    int c = blockIdx.x, t = threadIdx.x;
    int f0 = c % 5, f1 = (c / 5) % 5, f2 = c / 25;
    combo[c * HH + t] = bemb[f0 * HH + t] + bemb[(5 + f1) * HH + t] + bemb[(10 + f2) * HH + t];
}

__global__ void embed_kernel(const float* __restrict__ aemb, const int* __restrict__ nf,
                             float* __restrict__ h0) {
    int n = blockIdx.x, t = threadIdx.x;
    float acc = 0.0f;
#pragma unroll
    for (int j = 0; j < 9; j++) acc += aemb[(nf[n * 9 + j] + j * 16) * HH + t];
    h0[n * HH + t] = acc;
    split_bf(acc, g_hhi[n * HH + t], g_hlo[n * HH + t]);
}

__global__ void ctab_kernel(const float* __restrict__ combo, const float* __restrict__ We,
                            const float* __restrict__ bias) {
    __shared__ float s[HH];
    int c = blockIdx.x, t = threadIdx.x;
    s[t] = combo[c * HH + t];
    __syncthreads();
    float acc = bias[t];
#pragma unroll 8
    for (int k = 0; k < HH; k++) acc += s[k] * We[k * HH + t];
    g_Ctab[c * HH + t] = acc;
}

// ================= weight prepacks (fp32 -> bf16 hi/lo, n-major) =================
__global__ void pack_wsd_kernel(const float* __restrict__ wpre,
                                __nv_bfloat16* __restrict__ ohi, __nv_bfloat16* __restrict__ olo) {
    int idx = blockIdx.x * blockDim.x + threadIdx.x;
    if (idx >= LL * 256 * 128) return;
    int l = idx / (256 * 128);
    int rem = idx % (256 * 128);
    int c = rem / 128, k = rem % 128;
    float w = wpre[l * 49152 + ((c >> 7) * 128 + k) * 128 + (c & 127)];
    split_bf(w, ohi[idx], olo[idx]);
}

__global__ void pack_wbig_kernel(const float* __restrict__ wpost,
                                 __nv_bfloat16* __restrict__ ohi, __nv_bfloat16* __restrict__ olo) {
    int idx = blockIdx.x * blockDim.x + threadIdx.x;
    if (idx >= LL * 384 * 640) return;
    int l = idx / (384 * 640);
    int rem = idx % (384 * 640);
    int c = rem / 640, k = rem % 640;
    int p = c >> 7, j = c & 127;
    float w;
    if (k < 128) w = (p == 0) ? wpost[l * 212992 + k * 128 + j] : 0.0f;
    else w = wpost[l * 212992 + (128 + p * 512 + (k - 128)) * 128 + j];
    split_bf(w, ohi[idx], olo[idx]);
}

// ================= edge aggregation (warp per node) =================
__device__ __forceinline__ void split4(float4 v, uint2& hi, uint2& lo) {
    __nv_bfloat16 hx, lx, hy, ly, hz, lz, hw, lw;
    split_bf(v.x, hx, lx); split_bf(v.y, hy, ly);
    split_bf(v.z, hz, lz); split_bf(v.w, hw, lw);
    __nv_bfloat162 h0 = __halves2bfloat162(hx, hy), h1 = __halves2bfloat162(hz, hw);
    __nv_bfloat162 l0 = __halves2bfloat162(lx, ly), l1 = __halves2bfloat162(lz, lw);
    hi.x = *(uint32_t*)&h0; hi.y = *(uint32_t*)&h1;
    lo.x = *(uint32_t*)&l0; lo.y = *(uint32_t*)&l1;
}

__global__ void aggregate_kernel() {
    int node = blockIdx.x * 8 + (threadIdx.x >> 5);
    if (node >= NN) return;
    int lane = threadIdx.x & 31;
    int h4 = lane * 4;
    float4 b4 = *(const float4*)&g_AB[(size_t)node * 256 + 128 + h4];
    float sx = 0, sy = 0, sz = 0, sw = 0;
    float qx = 0, qy = 0, qz = 0, qw = 0;
    float mxx = -1e30f, mxy = -1e30f, mxz = -1e30f, mxw = -1e30f;
    float mnx = 1e30f, mny = 1e30f, mnz = 1e30f, mnw = 1e30f;
    int start = g_rowptr[node], end = g_rowptr[node + 1];
    for (int i = start; i < end; i++) {
        int packed = g_elist[i];
        int s = packed & 0xFFFF;
        int c = packed >> 16;
        float4 a4 = *(const float4*)&g_AB[(size_t)s * 256 + h4];
        float4 c4 = *(const float4*)&g_Ctab[c * HH + h4];
        float zx = a4.x + b4.x + c4.x;
        float zy = a4.y + b4.y + c4.y;
        float zz = a4.z + b4.z + c4.z;
        float zw = a4.w + b4.w + c4.w;
        sx += zx; sy += zy; sz += zz; sw += zw;
        qx += zx * zx; qy += zy * zy; qz += zz * zz; qw += zw * zw;
        mxx = fmaxf(mxx, zx); mxy = fmaxf(mxy, zy); mxz = fmaxf(mxz, zz); mxw = fmaxf(mxw, zw);
        mnx = fminf(mnx, zx); mny = fminf(mny, zy); mnz = fminf(mnz, zz); mnw = fminf(mnw, zw);
    }
    __nv_bfloat16* ohi = &g_HAhi[(size_t)node * 640];
    __nv_bfloat16* olo = &g_HAlo[(size_t)node * 640];
    *(uint2*)&ohi[h4] = *(const uint2*)&g_hhi[node * HH + h4];
    *(uint2*)&olo[h4] = *(const uint2*)&g_hlo[node * HH + h4];
    float4 me, mx4, mn4, sd4;
    int deg = end - start;
    if (deg == 0) {
        me = mx4 = mn4 = sd4 = make_float4(0, 0, 0, 0);
    } else {
        float inv = 1.0f / (float)deg;
        me = make_float4(sx * inv, sy * inv, sz * inv, sw * inv);
        float vx = fmaxf(qx * inv - me.x * me.x, 0.0f);
        float vy = fmaxf(qy * inv - me.y * me.y, 0.0f);
        float vz = fmaxf(qz * inv - me.z * me.z, 0.0f);
        float vw = fmaxf(qw * inv - me.w * me.w, 0.0f);
        mx4 = make_float4(mxx, mxy, mxz, mxw);
        mn4 = make_float4(mnx, mny, mnz, mnw);
        sd4 = make_float4(sqrtf(vx + 1e-5f), sqrtf(vy + 1e-5f), sqrtf(vz + 1e-5f), sqrtf(vw + 1e-5f));
    }
    uint2 hi, lo;
    split4(me, hi, lo);  *(uint2*)&ohi[128 + h4] = hi; *(uint2*)&olo[128 + h4] = lo;
    split4(mx4, hi, lo); *(uint2*)&ohi[256 + h4] = hi; *(uint2*)&olo[256 + h4] = lo;
    split4(mn4, hi, lo); *(uint2*)&ohi[384 + h4] = hi; *(uint2*)&olo[384 + h4] = lo;
    split4(sd4, hi, lo); *(uint2*)&ohi[512 + h4] = hi; *(uint2*)&olo[512 + h4] = lo;
}

__global__ void combine_kernel(const float* __restrict__ hcur, const float* __restrict__ bpost,
                               float* __restrict__ hnext) {
    int idx = blockIdx.x * blockDim.x + threadIdx.x;
    if (idx >= NN * HH) return;
    int n = idx >> 7;
    int h = idx & 127;
    const float* y = &g_Y[(size_t)n * 384];
    float v = y[h] + g_amp[n] * y[128 + h] + g_att[n] * y[256 + h] + bpost[h] + hcur[idx];
    hnext[idx] = v;
    split_bf(v, g_hhi[idx], g_hlo[idx]);
}

__global__ void readout_kernel(const float* __restrict__ h, float* __restrict__ out, int ldo) {
    int g = blockIdx.x, t = threadIdx.x;
    float mn = 1e30f, mx = -1e30f, s = 0.0f;
#pragma unroll
    for (int i = 0; i < NPGC; i++) {
        float v = h[(g * NPGC + i) * HH + t];
        mn = fminf(mn, v);
        mx = fmaxf(mx, v);
        s += v;
    }
    out[g * ldo + t] = mn;
    out[g * ldo + 128 + t] = mx;
    out[g * ldo + 256 + t] = s * (1.0f / (float)NPGC);
}

// ================= bf16 mma.sync 3-term GEMM =================
// C[M,NT] = (Ahi+Alo) @ Bhi^T + Ahi @ Blo^T
// A row-major [M, Ktot], B n-major [NT, Ktot]. CTA tile 128x128, BK=32,
// 8 warps (4 m x 2 n), warp tile 32x64, double-buffered padded SMEM.
#define APITCH 40   // halves per SMEM row (32 data + 8 pad = 80B pitch)

__device__ __forceinline__ void mma16816(float* c, const uint32_t* a, uint32_t b0, uint32_t b1) {
    asm volatile(
        "mma.sync.aligned.m16n8k16.row.col.f32.bf16.bf16.f32 "
        "{%0,%1,%2,%3}, {%4,%5,%6,%7}, {%8,%9}, {%0,%1,%2,%3};"
        : "+f"(c[0]), "+f"(c[1]), "+f"(c[2]), "+f"(c[3])
        : "r"(a[0]), "r"(a[1]), "r"(a[2]), "r"(a[3]), "r"(b0), "r"(b1));
}

__global__ __launch_bounds__(256) void gemm_mma_kernel(
    const __nv_bfloat16* __restrict__ Ahi, const __nv_bfloat16* __restrict__ Alo,
    const __nv_bfloat16* __restrict__ Bhi, const __nv_bfloat16* __restrict__ Blo,
    float* __restrict__ C, int M, int Ktot, int NT) {
    __shared__ __nv_bfloat16 As[2][128 * APITCH];
    __shared__ __nv_bfloat16 Bs[2][128 * APITCH];
    int tid = threadIdx.x;
    int wid = tid >> 5, lane = tid & 31;
    int warp_m = wid & 3, warp_n = wid >> 2;
    int m0 = blockIdx.x * 128;
    int n0 = blockIdx.y * 128;

    float acc[2][8][4];
#pragma unroll
    for (int mi = 0; mi < 2; mi++)
#pragma unroll
        for (int ni = 0; ni < 8; ni++)
#pragma unroll
            for (int q = 0; q < 4; q++) acc[mi][ni][q] = 0.0f;

    const int cpseg = Ktot >> 5;
    const int nch = 3 * cpseg;
    int lr = tid >> 2, lc = (tid & 3) * 8;   // each thread: rows lr, lr+64; 16B chunk at lc

#define LOAD_CHUNK(i, buf) do { \
    int seg_ = (i) / cpseg; \
    int kb_ = ((i) - seg_ * cpseg) << 5; \
    const __nv_bfloat16* Ap_ = (seg_ == 1) ? Alo : Ahi; \
    const __nv_bfloat16* Bp_ = (seg_ == 2) ? Blo : Bhi; \
    _Pragma("unroll") \
    for (int j_ = 0; j_ < 2; j_++) { \
        int r_ = lr + j_ * 64; \
        float4 av_ = make_float4(0.f, 0.f, 0.f, 0.f); \
        int m_ = m0 + r_; \
        if (m_ < M) av_ = *(const float4*)(Ap_ + (size_t)m_ * Ktot + kb_ + lc); \
        *(float4*)&As[buf][r_ * APITCH + lc] = av_; \
        float4 bv_ = *(const float4*)(Bp_ + (size_t)(n0 + r_) * Ktot + kb_ + lc); \
        *(float4*)&Bs[buf][r_ * APITCH + lc] = bv_; \
    } } while (0)

    LOAD_CHUNK(0, 0);
    __syncthreads();

    int arow = warp_m * 32 + (lane >> 2);
    int acolb = (lane & 3) * 2;
    int brow = warp_n * 64 + (lane >> 2);

    for (int i = 0; i < nch; i++) {
        int buf = i & 1;
        if (i + 1 < nch) LOAD_CHUNK(i + 1, (i + 1) & 1);
#pragma unroll
        for (int kk = 0; kk < 32; kk += 16) {
            uint32_t af[2][4];
#pragma unroll
            for (int mi = 0; mi < 2; mi++) {
                int r = arow + mi * 16;
                int c = kk + acolb;
                af[mi][0] = *(const uint32_t*)&As[buf][r * APITCH + c];
                af[mi][1] = *(const uint32_t*)&As[buf][(r + 8) * APITCH + c];
                af[mi][2] = *(const uint32_t*)&As[buf][r * APITCH + c + 8];
                af[mi][3] = *(const uint32_t*)&As[buf][(r + 8) * APITCH + c + 8];
            }
#pragma unroll
            for (int ni = 0; ni < 8; ni++) {
                int n = brow + ni * 8;
                int c = kk + acolb;
                uint32_t b0 = *(const uint32_t*)&Bs[buf][n * APITCH + c];
                uint32_t b1 = *(const uint32_t*)&Bs[buf][n * APITCH + c + 8];
                mma16816(acc[0][ni], af[0], b0, b1);
                mma16816(acc[1][ni], af[1], b0, b1);
            }
        }
        __syncthreads();
    }

#pragma unroll
    for (int mi = 0; mi < 2; mi++) {
#pragma unroll
        for (int ni = 0; ni < 8; ni++) {
            int row = m0 + warp_m * 32 + mi * 16 + (lane >> 2);
            int col = n0 + warp_n * 64 + ni * 8 + (lane & 3) * 2;
            if (row < M)
                *(float2*)&C[(size_t)row * NT + col] = make_float2(acc[mi][ni][0], acc[mi][ni][1]);
            if (row + 8 < M)
                *(float2*)&C[(size_t)(row + 8) * NT + col] = make_float2(acc[mi][ni][2], acc[mi][ni][3]);
        }
    }
#undef LOAD_CHUNK
}

// ================= fp32 tiled GEMM for small head GEMMs =================
__global__ void gemm_kernel(const float* __restrict__ A, const float* __restrict__ B,
                            float* __restrict__ C, const float* __restrict__ bias,
                            int M, int N, int K, int ldc, int relu) {
    __shared__ float As[16][64];
    __shared__ float Bs[16][64];
    int tid = threadIdx.x;
    int tx = tid & 15, ty = tid >> 4;
    int row0 = blockIdx.y * 64, col0 = blockIdx.x * 64;
    float acc[4][4];
#pragma unroll
    for (int i = 0; i < 4; i++)
#pragma unroll
        for (int j = 0; j < 4; j++) acc[i][j] = 0.0f;
    int ar = tid >> 2, ac = (tid & 3) * 4;
    int br = tid >> 4, bc = (tid & 15) * 4;
    int arow = row0 + ar;
    for (int k0 = 0; k0 < K; k0 += 16) {
        float4 a4 = make_float4(0, 0, 0, 0);
        if (arow < M) a4 = *(const float4*)&A[arow * K + k0 + ac];
        As[ac + 0][ar] = a4.x; As[ac + 1][ar] = a4.y; As[ac + 2][ar] = a4.z; As[ac + 3][ar] = a4.w;
        *(float4*)&Bs[br][bc] = *(const float4*)&B[(k0 + br) * N + col0 + bc];
        __syncthreads();
#pragma unroll
        for (int k = 0; k < 16; k++) {
            float4 av = *(const float4*)&As[k][ty * 4];
            float4 bv = *(const float4*)&Bs[k][tx * 4];
            acc[0][0] += av.x * bv.x; acc[0][1] += av.x * bv.y; acc[0][2] += av.x * bv.z; acc[0][3] += av.x * bv.w;
            acc[1][0] += av.y * bv.x; acc[1][1] += av.y * bv.y; acc[1][2] += av.y * bv.z; acc[1][3] += av.y * bv.w;
            acc[2][0] += av.z * bv.x; acc[2][1] += av.z * bv.y; acc[2][2] += av.z * bv.z; acc[2][3] += av.z * bv.w;
            acc[3][0] += av.w * bv.x; acc[3][1] += av.w * bv.y; acc[3][2] += av.w * bv.z; acc[3][3] += av.w * bv.w;
        }
        __syncthreads();
    }
#pragma unroll
    for (int i = 0; i < 4; i++) {
        int r = row0 + ty * 4 + i;
        if (r >= M) continue;
#pragma unroll
        for (int j = 0; j < 4; j++) {
            int col = col0 + tx * 4 + j;
            float v = acc[i][j];
            if (bias) v += bias[col];
            if (relu) v = fmaxf(v, 0.0f);
            C[r * ldc + col] = v;
        }
    }
}

static void launch_gemm(const float* A, const float* B, float* C, const float* bias,
                        int M, int N, int K, int ldc, int relu) {
    dim3 grid(N / 64, (M + 63) / 64);
    gemm_kernel<<<grid, 256>>>(A, B, C, bias, M, N, K, ldc, relu);
}

// ================= host =================
extern "C" void kernel_launch(void* const* d_in, const int* in_sizes, int n_in,
                              void* d_out, int out_size) {
    const int *node_feat = 0, *edge_feat = 0, *srcp = 0, *dstp = 0;
    const float *aemb_f = 0, *bemb_f = 0, *wpre_f = 0, *bpre_f = 0, *wpost_f = 0, *bpost_f = 0;
    const float *wout3 = 0, *bout3 = 0;
    const float *aemb = 0, *bemb = 0, *wpre = 0, *bpre = 0, *wpost = 0, *bpost = 0;
    const float *w1 = 0, *b1 = 0, *w2 = 0, *b2 = 0;
    int c400k = 0, c18432 = 0, c1920 = 0, c245760 = 0, c640 = 0, c1064960 = 0, c128 = 0;
    for (int i = 0; i < n_in; i++) {
        int sz = in_sizes[i];
        void* p = d_in[i];
        switch (sz) {
            case 450000: node_feat = (const int*)p; break;
            case 1200000: edge_feat = (const int*)p; break;
            case 400000: if (c400k++ == 0) srcp = (const int*)p; else dstp = (const int*)p; break;
            case 50000: break;
            case 18432: if (c18432++ == 0) aemb_f = (const float*)p; else aemb = (const float*)p; break;
            case 1920: if (c1920++ == 0) bemb_f = (const float*)p; else bemb = (const float*)p; break;
            case 245760: if (c245760++ == 0) wpre_f = (const float*)p; else wpre = (const float*)p; break;
            case 640: {
                int k = c640++;
                if (k == 0) bpre_f = (const float*)p;
                else if (k == 1) bpost_f = (const float*)p;
                else if (k == 2) bpre = (const float*)p;
                else bpost = (const float*)p;
            } break;
            case 1064960: if (c1064960++ == 0) wpost_f = (const float*)p; else wpost = (const float*)p; break;
            case 98304: wout3 = (const float*)p; break;
            case 256: bout3 = (const float*)p; break;
            case 81920: w1 = (const float*)p; break;
            case 128: if (c128++ == 0) b1 = (const float*)p; else b2 = (const float*)p; break;
            case 16384: w2 = (const float*)p; break;
            default: break;
        }
    }

    float *AB, *Y, *h0b, *h1b, *combo, *R3, *XB, *H1;
    __nv_bfloat16 *HAhi, *HAlo, *WsdHi, *WsdLo, *WbigHi, *WbigLo, *hhi, *hlo;
    int *deg, *cursor;
    cudaGetSymbolAddress((void**)&AB, g_AB);
    cudaGetSymbolAddress((void**)&Y, g_Y);
    cudaGetSymbolAddress((void**)&h0b, g_hbuf0);
    cudaGetSymbolAddress((void**)&h1b, g_hbuf1);
    cudaGetSymbolAddress((void**)&combo, g_combo);
    cudaGetSymbolAddress((void**)&R3, g_R3);
    cudaGetSymbolAddress((void**)&XB, g_XB);
    cudaGetSymbolAddress((void**)&H1, g_H1);
    cudaGetSymbolAddress((void**)&HAhi, g_HAhi);
    cudaGetSymbolAddress((void**)&HAlo, g_HAlo);
    cudaGetSymbolAddress((void**)&WsdHi, g_WsdHi);
    cudaGetSymbolAddress((void**)&WsdLo, g_WsdLo);
    cudaGetSymbolAddress((void**)&WbigHi, g_WbigHi);
    cudaGetSymbolAddress((void**)&WbigLo, g_WbigLo);
    cudaGetSymbolAddress((void**)&hhi, g_hhi);
    cudaGetSymbolAddress((void**)&hlo, g_hlo);
    cudaGetSymbolAddress((void**)&deg, g_deg);
    cudaGetSymbolAddress((void**)&cursor, g_cursor);

    cudaMemsetAsync(deg, 0, NN * sizeof(int));
    cudaMemsetAsync(cursor, 0, NN * sizeof(int));
    count_kernel<<<(EE + 255) / 256, 256>>>(dstp);
    scan_kernel<<<1, 1024>>>();
    scalars_kernel<<<(NN + 255) / 256, 256>>>();
    fill_kernel<<<(EE + 255) / 256, 256>>>(srcp, dstp, edge_feat);

    const float* bembs[2] = { bemb_f, bemb };
    const float* aembs[2] = { aemb_f, aemb };
    const float* wpres[2] = { wpre_f, wpre };
    const float* bpres[2] = { bpre_f, bpre };
    const float* wposts[2] = { wpost_f, wpost };
    const float* bposts[2] = { bpost_f, bpost };
    for (int br = 0; br < 2; br++) {
        combo_kernel<<<125, 128>>>(bembs[br], combo + br * 125 * HH);
        pack_wsd_kernel<<<(LL * 256 * 128 + 255) / 256, 256>>>(wpres[br],
            WsdHi + br * LL * 256 * 128, WsdLo + br * LL * 256 * 128);
        pack_wbig_kernel<<<(LL * 384 * 640 + 255) / 256, 256>>>(wposts[br],
            WbigHi + (size_t)br * LL * 384 * 640, WbigLo + (size_t)br * LL * 384 * 640);
    }

    const int MT = (NN + 127) / 128;   // 391

    for (int br = 0; br < 2; br++) {
        embed_kernel<<<NN, 128>>>(aembs[br], node_feat, h0b);
        float* hcur = h0b;
        float* hnext = h1b;
        for (int l = 0; l < LL; l++) {
            ctab_kernel<<<125, 128>>>(combo + br * 125 * HH,
                                      wpres[br] + l * 49152 + 256 * 128,
                                      bpres[br] + l * 128);
            gemm_mma_kernel<<<dim3(MT, 2), 256>>>(
                hhi, hlo,
                WsdHi + br * LL * 256 * 128 + l * 256 * 128,
                WsdLo + br * LL * 256 * 128 + l * 256 * 128,
                AB, NN, 128, 256);
            aggregate_kernel<<<(NN + 7) / 8, 256>>>();
            gemm_mma_kernel<<<dim3(MT, 3), 256>>>(
                HAhi, HAlo,
                WbigHi + (size_t)br * LL * 384 * 640 + (size_t)l * 384 * 640,
                WbigLo + (size_t)br * LL * 384 * 640 + (size_t)l * 384 * 640,
                Y, NN, 640, 384);
            combine_kernel<<<(NN * HH + 255) / 256, 256>>>(hcur, bposts[br] + l * 128, hnext);
            float* tmp = hcur; hcur = hnext; hnext = tmp;
        }
        if (br == 0) {
            readout_kernel<<<GG, 128>>>(hcur, R3, 384);
            launch_gemm(R3, wout3, XB + 384, bout3, GG, 256, 384, 640, 0);
        } else {
            readout_kernel<<<GG, 128>>>(hcur, XB, 640);
        }
    }

    launch_gemm(XB, w1, H1, b1, GG, 128, 640, 128, 1);
    launch_gemm(H1, w2, (float*)d_out, b2, GG, 128, 128, 128, 0);
    (void)out_size;
}

// round 4
// speedup vs baseline: 2.1337x; 1.2606x over previous
#include <cuda_runtime.h>
#include <cuda_bf16.h>
#include <cstdint>
#include <math.h>

#define NN 50000
#define EE 400000
#define GG 2000
#define HH 128
#define LL 5
#define NPGC 25

// ================= scratch (device globals) =================
__device__ __nv_bfloat16 g_HAhi[(size_t)NN * 640];
__device__ __nv_bfloat16 g_HAlo[(size_t)NN * 640];
__device__ __nv_bfloat16 g_hhi[NN * HH];
__device__ __nv_bfloat16 g_hlo[NN * HH];
__device__ float g_AB[(size_t)NN * 256];
__device__ float g_Y[(size_t)NN * 384];
__device__ float g_hbuf0[NN * HH];
__device__ float g_hbuf1[NN * HH];
__device__ __nv_bfloat16 g_WsdHi[2][LL * 256 * 128];
__device__ __nv_bfloat16 g_WsdLo[2][LL * 256 * 128];
__device__ __nv_bfloat16 g_WbigHi[2][LL * 384 * 640];
__device__ __nv_bfloat16 g_WbigLo[2][LL * 384 * 640];
__device__ float g_combo[2][125 * HH];
__device__ float g_Ctab[125 * HH];
__device__ int   g_deg[NN];
__device__ int   g_rowptr[NN + 1];
__device__ int   g_cursor[NN];
__device__ int   g_elist[EE];
__device__ float g_amp[NN];
__device__ float g_att[NN];
__device__ float g_R3[GG * 384];
__device__ float g_XB[GG * 640];
__device__ float g_H1[GG * HH];

__device__ __forceinline__ void split_bf(float x, __nv_bfloat16& h, __nv_bfloat16& l) {
    h = __float2bfloat16_rn(x);
    l = __float2bfloat16_rn(x - __bfloat162float(h));
}

__device__ __forceinline__ uint32_t smem_u32(const void* p) {
    uint32_t a;
    asm("{ .reg .u64 t; cvta.to.shared.u64 t, %1; cvt.u32.u64 %0, t; }" : "=r"(a) : "l"(p));
    return a;
}

// ================= graph preprocessing =================
__global__ void count_kernel(const int* __restrict__ dst) {
    int e = blockIdx.x * blockDim.x + threadIdx.x;
    if (e < EE) atomicAdd(&g_deg[dst[e]], 1);
}

__global__ void scan_kernel() {
    __shared__ int part[1024];
    int t = threadIdx.x;
    const int CH = (NN + 1023) / 1024;
    int base = t * CH;
    int s = 0;
    for (int i = 0; i < CH; i++) { int idx = base + i; if (idx < NN) s += g_deg[idx]; }
    part[t] = s;
    __syncthreads();
    for (int off = 1; off < 1024; off <<= 1) {
        int v = (t >= off) ? part[t - off] : 0;
        __syncthreads();
        part[t] += v;
        __syncthreads();
    }
    int run = (t == 0) ? 0 : part[t - 1];
    for (int i = 0; i < CH; i++) {
        int idx = base + i;
        if (idx < NN) { g_rowptr[idx] = run; run += g_deg[idx]; }
    }
    if (t == 1023) g_rowptr[NN] = part[1023];
}

__global__ void scalars_kernel() {
    int n = blockIdx.x * blockDim.x + threadIdx.x;
    if (n >= NN) return;
    int d = g_deg[n];
    float ld = logf((float)d + 1.0f);
    g_amp[n] = ld;
    g_att[n] = (d > 0) ? (1.0f / ld) : 0.0f;
}

__global__ void fill_kernel(const int* __restrict__ src, const int* __restrict__ dst,
                            const int* __restrict__ ef) {
    int e = blockIdx.x * blockDim.x + threadIdx.x;
    if (e >= EE) return;
    int d = dst[e];
    int pos = g_rowptr[d] + atomicAdd(&g_cursor[d], 1);
    int c = ef[e * 3 + 0] + 5 * ef[e * 3 + 1] + 25 * ef[e * 3 + 2];
    g_elist[pos] = src[e] | (c << 16);
}

__global__ void combo_kernel(const float* __restrict__ bemb, float* __restrict__ combo) {
    int c = blockIdx.x, t = threadIdx.x;
    int f0 = c % 5, f1 = (c / 5) % 5, f2 = c / 25;
    combo[c * HH + t] = bemb[f0 * HH + t] + bemb[(5 + f1) * HH + t] + bemb[(10 + f2) * HH + t];
}

__global__ void embed_kernel(const float* __restrict__ aemb, const int* __restrict__ nf,
                             float* __restrict__ h0) {
    int n = blockIdx.x, t = threadIdx.x;
    float acc = 0.0f;
#pragma unroll
    for (int j = 0; j < 9; j++) acc += aemb[(nf[n * 9 + j] + j * 16) * HH + t];
    h0[n * HH + t] = acc;
    split_bf(acc, g_hhi[n * HH + t], g_hlo[n * HH + t]);
}

__global__ void ctab_kernel(const float* __restrict__ combo, const float* __restrict__ We,
                            const float* __restrict__ bias) {
    __shared__ float s[HH];
    int c = blockIdx.x, t = threadIdx.x;
    s[t] = combo[c * HH + t];
    __syncthreads();
    float acc = bias[t];
#pragma unroll 8
    for (int k = 0; k < HH; k++) acc += s[k] * We[k * HH + t];
    g_Ctab[c * HH + t] = acc;
}

// ================= weight prepacks (fp32 -> bf16 hi/lo, n-major) =================
__global__ void pack_wsd_kernel(const float* __restrict__ wpre,
                                __nv_bfloat16* __restrict__ ohi, __nv_bfloat16* __restrict__ olo) {
    int idx = blockIdx.x * blockDim.x + threadIdx.x;
    if (idx >= LL * 256 * 128) return;
    int l = idx / (256 * 128);
    int rem = idx % (256 * 128);
    int c = rem / 128, k = rem % 128;
    float w = wpre[l * 49152 + ((c >> 7) * 128 + k) * 128 + (c & 127)];
    split_bf(w, ohi[idx], olo[idx]);
}

__global__ void pack_wbig_kernel(const float* __restrict__ wpost,
                                 __nv_bfloat16* __restrict__ ohi, __nv_bfloat16* __restrict__ olo) {
    int idx = blockIdx.x * blockDim.x + threadIdx.x;
    if (idx >= LL * 384 * 640) return;
    int l = idx / (384 * 640);
    int rem = idx % (384 * 640);
    int c = rem / 640, k = rem % 640;
    int p = c >> 7, j = c & 127;
    float w;
    if (k < 128) w = (p == 0) ? wpost[l * 212992 + k * 128 + j] : 0.0f;
    else w = wpost[l * 212992 + (128 + p * 512 + (k - 128)) * 128 + j];
    split_bf(w, ohi[idx], olo[idx]);
}

// ================= edge aggregation (warp per node) =================
__device__ __forceinline__ void split4(float4 v, uint2& hi, uint2& lo) {
    __nv_bfloat16 hx, lx, hy, ly, hz, lz, hw, lw;
    split_bf(v.x, hx, lx); split_bf(v.y, hy, ly);
    split_bf(v.z, hz, lz); split_bf(v.w, hw, lw);
    __nv_bfloat162 h0 = __halves2bfloat162(hx, hy), h1 = __halves2bfloat162(hz, hw);
    __nv_bfloat162 l0 = __halves2bfloat162(lx, ly), l1 = __halves2bfloat162(lz, lw);
    hi.x = *(uint32_t*)&h0; hi.y = *(uint32_t*)&h1;
    lo.x = *(uint32_t*)&l0; lo.y = *(uint32_t*)&l1;
}

__global__ void aggregate_kernel() {
    int node = blockIdx.x * 8 + (threadIdx.x >> 5);
    if (node >= NN) return;
    int lane = threadIdx.x & 31;
    int h4 = lane * 4;
    float4 b4 = *(const float4*)&g_AB[(size_t)node * 256 + 128 + h4];
    float sx = 0, sy = 0, sz = 0, sw = 0;
    float qx = 0, qy = 0, qz = 0, qw = 0;
    float mxx = -1e30f, mxy = -1e30f, mxz = -1e30f, mxw = -1e30f;
    float mnx = 1e30f, mny = 1e30f, mnz = 1e30f, mnw = 1e30f;
    int start = g_rowptr[node], end = g_rowptr[node + 1];
    for (int i = start; i < end; i++) {
        int packed = g_elist[i];
        int s = packed & 0xFFFF;
        int c = packed >> 16;
        float4 a4 = *(const float4*)&g_AB[(size_t)s * 256 + h4];
        float4 c4 = *(const float4*)&g_Ctab[c * HH + h4];
        float zx = a4.x + b4.x + c4.x;
        float zy = a4.y + b4.y + c4.y;
        float zz = a4.z + b4.z + c4.z;
        float zw = a4.w + b4.w + c4.w;
        sx += zx; sy += zy; sz += zz; sw += zw;
        qx += zx * zx; qy += zy * zy; qz += zz * zz; qw += zw * zw;
        mxx = fmaxf(mxx, zx); mxy = fmaxf(mxy, zy); mxz = fmaxf(mxz, zz); mxw = fmaxf(mxw, zw);
        mnx = fminf(mnx, zx); mny = fminf(mny, zy); mnz = fminf(mnz, zz); mnw = fminf(mnw, zw);
    }
    __nv_bfloat16* ohi = &g_HAhi[(size_t)node * 640];
    __nv_bfloat16* olo = &g_HAlo[(size_t)node * 640];
    *(uint2*)&ohi[h4] = *(const uint2*)&g_hhi[node * HH + h4];
    *(uint2*)&olo[h4] = *(const uint2*)&g_hlo[node * HH + h4];
    float4 me, mx4, mn4, sd4;
    int deg = end - start;
    if (deg == 0) {
        me = mx4 = mn4 = sd4 = make_float4(0, 0, 0, 0);
    } else {
        float inv = 1.0f / (float)deg;
        me = make_float4(sx * inv, sy * inv, sz * inv, sw * inv);
        float vx = fmaxf(qx * inv - me.x * me.x, 0.0f);
        float vy = fmaxf(qy * inv - me.y * me.y, 0.0f);
        float vz = fmaxf(qz * inv - me.z * me.z, 0.0f);
        float vw = fmaxf(qw * inv - me.w * me.w, 0.0f);
        mx4 = make_float4(mxx, mxy, mxz, mxw);
        mn4 = make_float4(mnx, mny, mnz, mnw);
        sd4 = make_float4(sqrtf(vx + 1e-5f), sqrtf(vy + 1e-5f), sqrtf(vz + 1e-5f), sqrtf(vw + 1e-5f));
    }
    uint2 hi, lo;
    split4(me, hi, lo);  *(uint2*)&ohi[128 + h4] = hi; *(uint2*)&olo[128 + h4] = lo;
    split4(mx4, hi, lo); *(uint2*)&ohi[256 + h4] = hi; *(uint2*)&olo[256 + h4] = lo;
    split4(mn4, hi, lo); *(uint2*)&ohi[384 + h4] = hi; *(uint2*)&olo[384 + h4] = lo;
    split4(sd4, hi, lo); *(uint2*)&ohi[512 + h4] = hi; *(uint2*)&olo[512 + h4] = lo;
}

__global__ void combine_kernel(const float* __restrict__ hcur, const float* __restrict__ bpost,
                               float* __restrict__ hnext) {
    int idx = blockIdx.x * blockDim.x + threadIdx.x;
    if (idx >= NN * HH) return;
    int n = idx >> 7;
    int h = idx & 127;
    const float* y = &g_Y[(size_t)n * 384];
    float v = y[h] + g_amp[n] * y[128 + h] + g_att[n] * y[256 + h] + bpost[h] + hcur[idx];
    hnext[idx] = v;
    split_bf(v, g_hhi[idx], g_hlo[idx]);
}

__global__ void readout_kernel(const float* __restrict__ h, float* __restrict__ out, int ldo) {
    int g = blockIdx.x, t = threadIdx.x;
    float mn = 1e30f, mx = -1e30f, s = 0.0f;
#pragma unroll
    for (int i = 0; i < NPGC; i++) {
        float v = h[(g * NPGC + i) * HH + t];
        mn = fminf(mn, v);
        mx = fmaxf(mx, v);
        s += v;
    }
    out[g * ldo + t] = mn;
    out[g * ldo + 128 + t] = mx;
    out[g * ldo + 256 + t] = s * (1.0f / (float)NPGC);
}

// ================= bf16 mma.sync 3-term GEMM (cp.async + ldmatrix) =================
// C[M,NT] = (Ahi+Alo) @ Bhi^T + Ahi @ Blo^T
// A row-major [M,Ktot], B n-major [NT,Ktot]. CTA tile 128x128, BK=32,
// 8 warps (4m x 2n), warp tile 32x64, double-buffered SMEM w/ 80B pitch.
#define APITCH 40   // bf16 elems per SMEM row (32 data + 8 pad = 80B pitch)

__device__ __forceinline__ void mma16816(float* c, const uint32_t* a, uint32_t b0, uint32_t b1) {
    asm volatile(
        "mma.sync.aligned.m16n8k16.row.col.f32.bf16.bf16.f32 "
        "{%0,%1,%2,%3}, {%4,%5,%6,%7}, {%8,%9}, {%0,%1,%2,%3};"
        : "+f"(c[0]), "+f"(c[1]), "+f"(c[2]), "+f"(c[3])
        : "r"(a[0]), "r"(a[1]), "r"(a[2]), "r"(a[3]), "r"(b0), "r"(b1));
}
#define LDMX4(r, addr) \
    asm volatile("ldmatrix.sync.aligned.m8n8.x4.shared.b16 {%0,%1,%2,%3}, [%4];" \
        : "=r"((r)[0]), "=r"((r)[1]), "=r"((r)[2]), "=r"((r)[3]) : "r"(addr))
#define CP16(dst, src, sz) \
    asm volatile("cp.async.cg.shared.global [%0], [%1], 16, %2;" :: "r"(dst), "l"(src), "r"(sz))
#define CP_COMMIT() asm volatile("cp.async.commit_group;" ::: "memory")
#define CP_WAIT0() asm volatile("cp.async.wait_group 0;" ::: "memory")
#define CP_WAIT1() asm volatile("cp.async.wait_group 1;" ::: "memory")

__global__ __launch_bounds__(256) void gemm_mma_kernel(
    const __nv_bfloat16* __restrict__ Ahi, const __nv_bfloat16* __restrict__ Alo,
    const __nv_bfloat16* __restrict__ Bhi, const __nv_bfloat16* __restrict__ Blo,
    float* __restrict__ C, int M, int Ktot, int NT) {
    __shared__ __nv_bfloat16 As[2][128 * APITCH];
    __shared__ __nv_bfloat16 Bs[2][128 * APITCH];
    int tid = threadIdx.x;
    int wid = tid >> 5, lane = tid & 31;
    int warp_m = wid & 3, warp_n = wid >> 2;
    int n0 = blockIdx.x * 128;     // n-block first -> adjacent CTAs share A (L2 reuse)
    int m0 = blockIdx.y * 128;

    float acc[2][8][4];
#pragma unroll
    for (int mi = 0; mi < 2; mi++)
#pragma unroll
        for (int ni = 0; ni < 8; ni++)
#pragma unroll
            for (int q = 0; q < 4; q++) acc[mi][ni][q] = 0.0f;

    const int cpseg = Ktot >> 5;
    const int nch = 3 * cpseg;

    uint32_t asb[2] = { smem_u32(As[0]), smem_u32(As[1]) };
    uint32_t bsb[2] = { smem_u32(Bs[0]), smem_u32(Bs[1]) };

    // cp.async mapping: 512 16B-slots per tile; thread does slots tid, tid+256.
    // slot -> row = slot>>2, c16 = slot&3.
#define LOAD_CHUNK(i, buf) do { \
    int seg_ = (i) / cpseg; \
    int kb_ = ((i) - seg_ * cpseg) << 5; \
    const __nv_bfloat16* Ap_ = (seg_ == 1) ? Alo : Ahi; \
    const __nv_bfloat16* Bp_ = (seg_ == 2) ? Blo : Bhi; \
    _Pragma("unroll") \
    for (int q_ = 0; q_ < 2; q_++) { \
        int slot_ = tid + q_ * 256; \
        int row_ = slot_ >> 2, c16_ = slot_ & 3; \
        int m_ = m0 + row_; \
        int ok_ = (m_ < M) ? 16 : 0; \
        int mc_ = (m_ < M) ? m_ : 0; \
        CP16(asb[buf] + row_ * 80 + c16_ * 16, \
             Ap_ + (size_t)mc_ * Ktot + kb_ + c16_ * 8, ok_); \
        CP16(bsb[buf] + row_ * 80 + c16_ * 16, \
             Bp_ + (size_t)(n0 + row_) * Ktot + kb_ + c16_ * 8, 16); \
    } \
    CP_COMMIT(); \
} while (0)

    // ldmatrix per-thread byte offsets (within a buffer)
    uint32_t aRowOff = (uint32_t)((warp_m * 32 + (lane & 15)) * 80 + (lane >> 4) * 16);
    uint32_t bRowOff = (uint32_t)((warp_n * 64 + ((lane >> 4) << 3) + (lane & 7)) * 80 +
                                  ((lane >> 3) & 1) * 16);

    LOAD_CHUNK(0, 0);

    for (int i = 0; i < nch; i++) {
        int buf = i & 1;
        if (i + 1 < nch) {
            LOAD_CHUNK(i + 1, (i + 1) & 1);
            CP_WAIT1();
        } else {
            CP_WAIT0();
        }
        __syncthreads();
#pragma unroll
        for (int kk = 0; kk < 32; kk += 16) {
            uint32_t a[2][4];
#pragma unroll
            for (int mi = 0; mi < 2; mi++)
                LDMX4(a[mi], asb[buf] + aRowOff + (uint32_t)(mi * 16 * 80 + kk * 2));
            uint32_t bb[4][4];
#pragma unroll
            for (int p = 0; p < 4; p++)
                LDMX4(bb[p], bsb[buf] + bRowOff + (uint32_t)(p * 16 * 80 + kk * 2));
#pragma unroll
            for (int ni = 0; ni < 8; ni++) {
                int p = ni >> 1, h = (ni & 1) * 2;
                mma16816(acc[0][ni], a[0], bb[p][h], bb[p][h + 1]);
                mma16816(acc[1][ni], a[1], bb[p][h], bb[p][h + 1]);
            }
        }
        __syncthreads();
    }

#pragma unroll
    for (int mi = 0; mi < 2; mi++) {
#pragma unroll
        for (int ni = 0; ni < 8; ni++) {
            int row = m0 + warp_m * 32 + mi * 16 + (lane >> 2);
            int col = n0 + warp_n * 64 + ni * 8 + (lane & 3) * 2;
            if (row < M)
                *(float2*)&C[(size_t)row * NT + col] = make_float2(acc[mi][ni][0], acc[mi][ni][1]);
            if (row + 8 < M)
                *(float2*)&C[(size_t)(row + 8) * NT + col] = make_float2(acc[mi][ni][2], acc[mi][ni][3]);
        }
    }
#undef LOAD_CHUNK
}

// ================= fp32 tiled GEMM for small head GEMMs =================
__global__ void gemm_kernel(const float* __restrict__ A, const float* __restrict__ B,
                            float* __restrict__ C, const float* __restrict__ bias,
                            int M, int N, int K, int ldc, int relu) {
    __shared__ float As[16][64];
    __shared__ float Bs[16][64];
    int tid = threadIdx.x;
    int tx = tid & 15, ty = tid >> 4;
    int row0 = blockIdx.y * 64, col0 = blockIdx.x * 64;
    float acc[4][4];
#pragma unroll
    for (int i = 0; i < 4; i++)
#pragma unroll
        for (int j = 0; j < 4; j++) acc[i][j] = 0.0f;
    int ar = tid >> 2, ac = (tid & 3) * 4;
    int br = tid >> 4, bc = (tid & 15) * 4;
    int arow = row0 + ar;
    for (int k0 = 0; k0 < K; k0 += 16) {
        float4 a4 = make_float4(0, 0, 0, 0);
        if (arow < M) a4 = *(const float4*)&A[arow * K + k0 + ac];
        As[ac + 0][ar] = a4.x; As[ac + 1][ar] = a4.y; As[ac + 2][ar] = a4.z; As[ac + 3][ar] = a4.w;
        *(float4*)&Bs[br][bc] = *(const float4*)&B[(k0 + br) * N + col0 + bc];
        __syncthreads();
#pragma unroll
        for (int k = 0; k < 16; k++) {
            float4 av = *(const float4*)&As[k][ty * 4];
            float4 bv = *(const float4*)&Bs[k][tx * 4];
            acc[0][0] += av.x * bv.x; acc[0][1] += av.x * bv.y; acc[0][2] += av.x * bv.z; acc[0][3] += av.x * bv.w;
            acc[1][0] += av.y * bv.x; acc[1][1] += av.y * bv.y; acc[1][2] += av.y * bv.z; acc[1][3] += av.y * bv.w;
            acc[2][0] += av.z * bv.x; acc[2][1] += av.z * bv.y; acc[2][2] += av.z * bv.z; acc[2][3] += av.z * bv.w;
            acc[3][0] += av.w * bv.x; acc[3][1] += av.w * bv.y; acc[3][2] += av.w * bv.z; acc[3][3] += av.w * bv.w;
        }
        __syncthreads();
    }
#pragma unroll
    for (int i = 0; i < 4; i++) {
        int r = row0 + ty * 4 + i;
        if (r >= M) continue;
#pragma unroll
        for (int j = 0; j < 4; j++) {
            int col = col0 + tx * 4 + j;
            float v = acc[i][j];
            if (bias) v += bias[col];
            if (relu) v = fmaxf(v, 0.0f);
            C[r * ldc + col] = v;
        }
    }
}

static void launch_gemm(const float* A, const float* B, float* C, const float* bias,
                        int M, int N, int K, int ldc, int relu) {
    dim3 grid(N / 64, (M + 63) / 64);
    gemm_kernel<<<grid, 256>>>(A, B, C, bias, M, N, K, ldc, relu);
}

// ================= host =================
extern "C" void kernel_launch(void* const* d_in, const int* in_sizes, int n_in,
                              void* d_out, int out_size) {
    const int *node_feat = 0, *edge_feat = 0, *srcp = 0, *dstp = 0;
    const float *aemb_f = 0, *bemb_f = 0, *wpre_f = 0, *bpre_f = 0, *wpost_f = 0, *bpost_f = 0;
    const float *wout3 = 0, *bout3 = 0;
    const float *aemb = 0, *bemb = 0, *wpre = 0, *bpre = 0, *wpost = 0, *bpost = 0;
    const float *w1 = 0, *b1 = 0, *w2 = 0, *b2 = 0;
    int c400k = 0, c18432 = 0, c1920 = 0, c245760 = 0, c640 = 0, c1064960 = 0, c128 = 0;
    for (int i = 0; i < n_in; i++) {
        int sz = in_sizes[i];
        void* p = d_in[i];
        switch (sz) {
            case 450000: node_feat = (const int*)p; break;
            case 1200000: edge_feat = (const int*)p; break;
            case 400000: if (c400k++ == 0) srcp = (const int*)p; else dstp = (const int*)p; break;
            case 50000: break;
            case 18432: if (c18432++ == 0) aemb_f = (const float*)p; else aemb = (const float*)p; break;
            case 1920: if (c1920++ == 0) bemb_f = (const float*)p; else bemb = (const float*)p; break;
            case 245760: if (c245760++ == 0) wpre_f = (const float*)p; else wpre = (const float*)p; break;
            case 640: {
                int k = c640++;
                if (k == 0) bpre_f = (const float*)p;
                else if (k == 1) bpost_f = (const float*)p;
                else if (k == 2) bpre = (const float*)p;
                else bpost = (const float*)p;
            } break;
            case 1064960: if (c1064960++ == 0) wpost_f = (const float*)p; else wpost = (const float*)p; break;
            case 98304: wout3 = (const float*)p; break;
            case 256: bout3 = (const float*)p; break;
            case 81920: w1 = (const float*)p; break;
            case 128: if (c128++ == 0) b1 = (const float*)p; else b2 = (const float*)p; break;
            case 16384: w2 = (const float*)p; break;
            default: break;
        }
    }

    float *AB, *Y, *h0b, *h1b, *combo, *R3, *XB, *H1;
    __nv_bfloat16 *HAhi, *HAlo, *WsdHi, *WsdLo, *WbigHi, *WbigLo, *hhi, *hlo;
    int *deg, *cursor;
    cudaGetSymbolAddress((void**)&AB, g_AB);
    cudaGetSymbolAddress((void**)&Y, g_Y);
    cudaGetSymbolAddress((void**)&h0b, g_hbuf0);
    cudaGetSymbolAddress((void**)&h1b, g_hbuf1);
    cudaGetSymbolAddress((void**)&combo, g_combo);
    cudaGetSymbolAddress((void**)&R3, g_R3);
    cudaGetSymbolAddress((void**)&XB, g_XB);
    cudaGetSymbolAddress((void**)&H1, g_H1);
    cudaGetSymbolAddress((void**)&HAhi, g_HAhi);
    cudaGetSymbolAddress((void**)&HAlo, g_HAlo);
    cudaGetSymbolAddress((void**)&WsdHi, g_WsdHi);
    cudaGetSymbolAddress((void**)&WsdLo, g_WsdLo);
    cudaGetSymbolAddress((void**)&WbigHi, g_WbigHi);
    cudaGetSymbolAddress((void**)&WbigLo, g_WbigLo);
    cudaGetSymbolAddress((void**)&hhi, g_hhi);
    cudaGetSymbolAddress((void**)&hlo, g_hlo);
    cudaGetSymbolAddress((void**)&deg, g_deg);
    cudaGetSymbolAddress((void**)&cursor, g_cursor);

    cudaMemsetAsync(deg, 0, NN * sizeof(int));
    cudaMemsetAsync(cursor, 0, NN * sizeof(int));
    count_kernel<<<(EE + 255) / 256, 256>>>(dstp);
    scan_kernel<<<1, 1024>>>();
    scalars_kernel<<<(NN + 255) / 256, 256>>>();
    fill_kernel<<<(EE + 255) / 256, 256>>>(srcp, dstp, edge_feat);

    const float* bembs[2] = { bemb_f, bemb };
    const float* aembs[2] = { aemb_f, aemb };
    const float* wpres[2] = { wpre_f, wpre };
    const float* bpres[2] = { bpre_f, bpre };
    const float* wposts[2] = { wpost_f, wpost };
    const float* bposts[2] = { bpost_f, bpost };
    for (int br = 0; br < 2; br++) {
        combo_kernel<<<125, 128>>>(bembs[br], combo + br * 125 * HH);
        pack_wsd_kernel<<<(LL * 256 * 128 + 255) / 256, 256>>>(wpres[br],
            WsdHi + br * LL * 256 * 128, WsdLo + br * LL * 256 * 128);
        pack_wbig_kernel<<<(LL * 384 * 640 + 255) / 256, 256>>>(wposts[br],
            WbigHi + (size_t)br * LL * 384 * 640, WbigLo + (size_t)br * LL * 384 * 640);
    }

    const int MT = (NN + 127) / 128;   // 391

    for (int br = 0; br < 2; br++) {
        embed_kernel<<<NN, 128>>>(aembs[br], node_feat, h0b);
        float* hcur = h0b;
        float* hnext = h1b;
        for (int l = 0; l < LL; l++) {
            ctab_kernel<<<125, 128>>>(combo + br * 125 * HH,
                                      wpres[br] + l * 49152 + 256 * 128,
                                      bpres[br] + l * 128);
            gemm_mma_kernel<<<dim3(2, MT), 256>>>(
                hhi, hlo,
                WsdHi + br * LL * 256 * 128 + l * 256 * 128,
                WsdLo + br * LL * 256 * 128 + l * 256 * 128,
                AB, NN, 128, 256);
            aggregate_kernel<<<(NN + 7) / 8, 256>>>();
            gemm_mma_kernel<<<dim3(3, MT), 256>>>(
                HAhi, HAlo,
                WbigHi + (size_t)br * LL * 384 * 640 + (size_t)l * 384 * 640,
                WbigLo + (size_t)br * LL * 384 * 640 + (size_t)l * 384 * 640,
                Y, NN, 640, 384);
            combine_kernel<<<(NN * HH + 255) / 256, 256>>>(hcur, bposts[br] + l * 128, hnext);
            float* tmp = hcur; hcur = hnext; hnext = tmp;
        }
        if (br == 0) {
            readout_kernel<<<GG, 128>>>(hcur, R3, 384);
            launch_gemm(R3, wout3, XB + 384, bout3, GG, 256, 384, 640, 0);
        } else {
            readout_kernel<<<GG, 128>>>(hcur, XB, 640);
        }
    }

    launch_gemm(XB, w1, H1, b1, GG, 128, 640, 128, 1);
    launch_gemm(H1, w2, (float*)d_out, b2, GG, 128, 128, 128, 0);
    (void)out_size;
}

// round 5
// speedup vs baseline: 2.1717x; 1.0178x over previous
#include <cuda_runtime.h>
#include <cuda_bf16.h>
#include <cstdint>
#include <math.h>

#define NN 50000
#define EE 400000
#define GG 2000
#define HH 128
#define LL 5
#define NPGC 25

// ================= scratch (device globals) =================
__device__ __nv_bfloat16 g_HAhi[(size_t)NN * 640];
__device__ __nv_bfloat16 g_HAlo[(size_t)NN * 640];
__device__ __nv_bfloat16 g_hhi[NN * HH];
__device__ __nv_bfloat16 g_hlo[NN * HH];
__device__ float g_AB[(size_t)NN * 256];
__device__ float g_hbuf0[NN * HH];
__device__ float g_hbuf1[NN * HH];
__device__ __nv_bfloat16 g_WsdHi[2][LL * 256 * 128];
__device__ __nv_bfloat16 g_WsdLo[2][LL * 256 * 128];
__device__ __nv_bfloat16 g_WbigHi[2][LL * 384 * 640];
__device__ __nv_bfloat16 g_WbigLo[2][LL * 384 * 640];
__device__ float g_combo[2][125 * HH];
__device__ float g_Ctab[2 * LL * 125 * HH];
__device__ int   g_deg[NN];
__device__ int   g_rowptr[NN + 1];
__device__ int   g_cursor[NN];
__device__ int   g_elist[EE];
__device__ float g_amp[NN];
__device__ float g_att[NN];
__device__ float g_R3[GG * 384];
__device__ float g_XB[GG * 640];
__device__ float g_H1[GG * HH];

__device__ __forceinline__ void split_bf(float x, __nv_bfloat16& h, __nv_bfloat16& l) {
    h = __float2bfloat16_rn(x);
    l = __float2bfloat16_rn(x - __bfloat162float(h));
}
__device__ __forceinline__ uint32_t smem_u32(const void* p) {
    uint32_t a;
    asm("{ .reg .u64 t; cvta.to.shared.u64 t, %1; cvt.u32.u64 %0, t; }" : "=r"(a) : "l"(p));
    return a;
}
__device__ __forceinline__ uint32_t pack_hi(float x, float y) {
    __nv_bfloat162 v = __floats2bfloat162_rn(x, y);
    return *(uint32_t*)&v;
}

// ================= graph preprocessing =================
__global__ void count_kernel(const int* __restrict__ dst) {
    int e = blockIdx.x * blockDim.x + threadIdx.x;
    if (e < EE) atomicAdd(&g_deg[dst[e]], 1);
}

__global__ void scan_kernel() {
    __shared__ int part[1024];
    int t = threadIdx.x;
    const int CH = (NN + 1023) / 1024;
    int base = t * CH;
    int s = 0;
    for (int i = 0; i < CH; i++) { int idx = base + i; if (idx < NN) s += g_deg[idx]; }
    part[t] = s;
    __syncthreads();
    for (int off = 1; off < 1024; off <<= 1) {
        int v = (t >= off) ? part[t - off] : 0;
        __syncthreads();
        part[t] += v;
        __syncthreads();
    }
    int run = (t == 0) ? 0 : part[t - 1];
    for (int i = 0; i < CH; i++) {
        int idx = base + i;
        if (idx < NN) { g_rowptr[idx] = run; run += g_deg[idx]; }
    }
    if (t == 1023) g_rowptr[NN] = part[1023];
}

__global__ void scalars_kernel() {
    int n = blockIdx.x * blockDim.x + threadIdx.x;
    if (n >= NN) return;
    int d = g_deg[n];
    float ld = logf((float)d + 1.0f);
    g_amp[n] = ld;
    g_att[n] = (d > 0) ? (1.0f / ld) : 0.0f;
}

__global__ void fill_kernel(const int* __restrict__ src, const int* __restrict__ dst,
                            const int* __restrict__ ef) {
    int e = blockIdx.x * blockDim.x + threadIdx.x;
    if (e >= EE) return;
    int d = dst[e];
    int pos = g_rowptr[d] + atomicAdd(&g_cursor[d], 1);
    int c = ef[e * 3 + 0] + 5 * ef[e * 3 + 1] + 25 * ef[e * 3 + 2];
    g_elist[pos] = src[e] | (c << 16);
}

__global__ void combo_kernel(const float* __restrict__ bemb, float* __restrict__ combo) {
    int c = blockIdx.x, t = threadIdx.x;
    int f0 = c % 5, f1 = (c / 5) % 5, f2 = c / 25;
    combo[c * HH + t] = bemb[f0 * HH + t] + bemb[(5 + f1) * HH + t] + bemb[(10 + f2) * HH + t];
}

__global__ void embed_kernel(const float* __restrict__ aemb, const int* __restrict__ nf,
                             float* __restrict__ h0) {
    int n = blockIdx.x, t = threadIdx.x;
    float acc = 0.0f;
#pragma unroll
    for (int j = 0; j < 9; j++) acc += aemb[(nf[n * 9 + j] + j * 16) * HH + t];
    h0[n * HH + t] = acc;
    split_bf(acc, g_hhi[n * HH + t], g_hlo[n * HH + t]);
}

// Ctab for all layers of one branch: grid (125, LL)
__global__ void ctab_kernel(const float* __restrict__ combo, const float* __restrict__ wpre,
                            const float* __restrict__ bpre, float* __restrict__ out) {
    __shared__ float s[HH];
    int c = blockIdx.x, l = blockIdx.y, t = threadIdx.x;
    s[t] = combo[c * HH + t];
    __syncthreads();
    const float* We = wpre + l * 49152 + 256 * 128;
    float acc = bpre[l * 128 + t];
#pragma unroll 8
    for (int k = 0; k < HH; k++) acc += s[k] * We[k * HH + t];
    out[(l * 125 + c) * HH + t] = acc;
}

// ================= weight prepacks (fp32 -> bf16 hi/lo, n-major) =================
__global__ void pack_wsd_kernel(const float* __restrict__ wpre,
                                __nv_bfloat16* __restrict__ ohi, __nv_bfloat16* __restrict__ olo) {
    int idx = blockIdx.x * blockDim.x + threadIdx.x;
    if (idx >= LL * 256 * 128) return;
    int l = idx / (256 * 128);
    int rem = idx % (256 * 128);
    int c = rem / 128, k = rem % 128;
    float w = wpre[l * 49152 + ((c >> 7) * 128 + k) * 128 + (c & 127)];
    split_bf(w, ohi[idx], olo[idx]);
}

__global__ void pack_wbig_kernel(const float* __restrict__ wpost,
                                 __nv_bfloat16* __restrict__ ohi, __nv_bfloat16* __restrict__ olo) {
    int idx = blockIdx.x * blockDim.x + threadIdx.x;
    if (idx >= LL * 384 * 640) return;
    int l = idx / (384 * 640);
    int rem = idx % (384 * 640);
    int c = rem / 640, k = rem % 640;
    int p = c >> 7, j = c & 127;
    float w;
    if (k < 128) w = (p == 0) ? wpost[l * 212992 + k * 128 + j] : 0.0f;
    else w = wpost[l * 212992 + (128 + p * 512 + (k - 128)) * 128 + j];
    split_bf(w, ohi[idx], olo[idx]);
}

// ================= edge aggregation (warp per node, 4x unrolled gather) =================
__device__ __forceinline__ void split4(float4 v, uint2& hi, uint2& lo) {
    __nv_bfloat16 hx, lx, hy, ly, hz, lz, hw, lw;
    split_bf(v.x, hx, lx); split_bf(v.y, hy, ly);
    split_bf(v.z, hz, lz); split_bf(v.w, hw, lw);
    __nv_bfloat162 h0 = __halves2bfloat162(hx, hy), h1 = __halves2bfloat162(hz, hw);
    __nv_bfloat162 l0 = __halves2bfloat162(lx, ly), l1 = __halves2bfloat162(lz, lw);
    hi.x = *(uint32_t*)&h0; hi.y = *(uint32_t*)&h1;
    lo.x = *(uint32_t*)&l0; lo.y = *(uint32_t*)&l1;
}

__global__ void aggregate_kernel(const float* __restrict__ ctab) {
    int node = blockIdx.x * 8 + (threadIdx.x >> 5);
    if (node >= NN) return;
    int lane = threadIdx.x & 31;
    int h4 = lane * 4;
    float4 b4 = *(const float4*)&g_AB[(size_t)node * 256 + 128 + h4];
    float sx = 0, sy = 0, sz = 0, sw = 0;
    float qx = 0, qy = 0, qz = 0, qw = 0;
    float mxx = -1e30f, mxy = -1e30f, mxz = -1e30f, mxw = -1e30f;
    float mnx = 1e30f, mny = 1e30f, mnz = 1e30f, mnw = 1e30f;
    int start = g_rowptr[node], end = g_rowptr[node + 1];

#define ACC_Z(a4, c4) do { \
    float zx = (a4).x + b4.x + (c4).x; \
    float zy = (a4).y + b4.y + (c4).y; \
    float zz = (a4).z + b4.z + (c4).z; \
    float zw = (a4).w + b4.w + (c4).w; \
    sx += zx; sy += zy; sz += zz; sw += zw; \
    qx += zx * zx; qy += zy * zy; qz += zz * zz; qw += zw * zw; \
    mxx = fmaxf(mxx, zx); mxy = fmaxf(mxy, zy); mxz = fmaxf(mxz, zz); mxw = fmaxf(mxw, zw); \
    mnx = fminf(mnx, zx); mny = fminf(mny, zy); mnz = fminf(mnz, zz); mnw = fminf(mnw, zw); \
} while (0)

    int i = start;
    for (; i + 4 <= end; i += 4) {
        int p0 = g_elist[i], p1 = g_elist[i + 1], p2 = g_elist[i + 2], p3 = g_elist[i + 3];
        float4 a0 = *(const float4*)&g_AB[(size_t)(p0 & 0xFFFF) * 256 + h4];
        float4 a1 = *(const float4*)&g_AB[(size_t)(p1 & 0xFFFF) * 256 + h4];
        float4 a2 = *(const float4*)&g_AB[(size_t)(p2 & 0xFFFF) * 256 + h4];
        float4 a3 = *(const float4*)&g_AB[(size_t)(p3 & 0xFFFF) * 256 + h4];
        float4 c0 = *(const float4*)&ctab[(p0 >> 16) * HH + h4];
        float4 c1 = *(const float4*)&ctab[(p1 >> 16) * HH + h4];
        float4 c2 = *(const float4*)&ctab[(p2 >> 16) * HH + h4];
        float4 c3 = *(const float4*)&ctab[(p3 >> 16) * HH + h4];
        ACC_Z(a0, c0); ACC_Z(a1, c1); ACC_Z(a2, c2); ACC_Z(a3, c3);
    }
    for (; i < end; i++) {
        int p = g_elist[i];
        float4 a4 = *(const float4*)&g_AB[(size_t)(p & 0xFFFF) * 256 + h4];
        float4 c4 = *(const float4*)&ctab[(p >> 16) * HH + h4];
        ACC_Z(a4, c4);
    }
#undef ACC_Z

    __nv_bfloat16* ohi = &g_HAhi[(size_t)node * 640];
    __nv_bfloat16* olo = &g_HAlo[(size_t)node * 640];
    *(uint2*)&ohi[h4] = *(const uint2*)&g_hhi[node * HH + h4];
    *(uint2*)&olo[h4] = *(const uint2*)&g_hlo[node * HH + h4];
    float4 me, mx4, mn4, sd4;
    int deg = end - start;
    if (deg == 0) {
        me = mx4 = mn4 = sd4 = make_float4(0, 0, 0, 0);
    } else {
        float inv = 1.0f / (float)deg;
        me = make_float4(sx * inv, sy * inv, sz * inv, sw * inv);
        float vx = fmaxf(qx * inv - me.x * me.x, 0.0f);
        float vy = fmaxf(qy * inv - me.y * me.y, 0.0f);
        float vz = fmaxf(qz * inv - me.z * me.z, 0.0f);
        float vw = fmaxf(qw * inv - me.w * me.w, 0.0f);
        mx4 = make_float4(mxx, mxy, mxz, mxw);
        mn4 = make_float4(mnx, mny, mnz, mnw);
        sd4 = make_float4(sqrtf(vx + 1e-5f), sqrtf(vy + 1e-5f), sqrtf(vz + 1e-5f), sqrtf(vw + 1e-5f));
    }
    uint2 hi, lo;
    split4(me, hi, lo);  *(uint2*)&ohi[128 + h4] = hi; *(uint2*)&olo[128 + h4] = lo;
    split4(mx4, hi, lo); *(uint2*)&ohi[256 + h4] = hi; *(uint2*)&olo[256 + h4] = lo;
    split4(mn4, hi, lo); *(uint2*)&ohi[384 + h4] = hi; *(uint2*)&olo[384 + h4] = lo;
    split4(sd4, hi, lo); *(uint2*)&ohi[512 + h4] = hi; *(uint2*)&olo[512 + h4] = lo;
}

__global__ void readout_kernel(const float* __restrict__ h, float* __restrict__ out, int ldo) {
    int g = blockIdx.x, t = threadIdx.x;
    float mn = 1e30f, mx = -1e30f, s = 0.0f;
#pragma unroll
    for (int i = 0; i < NPGC; i++) {
        float v = h[(g * NPGC + i) * HH + t];
        mn = fminf(mn, v);
        mx = fmaxf(mx, v);
        s += v;
    }
    out[g * ldo + t] = mn;
    out[g * ldo + 128 + t] = mx;
    out[g * ldo + 256 + t] = s * (1.0f / (float)NPGC);
}

// ================= mma helpers =================
__device__ __forceinline__ void mma16816(float* c, const uint32_t* a, uint32_t b0, uint32_t b1) {
    asm volatile(
        "mma.sync.aligned.m16n8k16.row.col.f32.bf16.bf16.f32 "
        "{%0,%1,%2,%3}, {%4,%5,%6,%7}, {%8,%9}, {%0,%1,%2,%3};"
        : "+f"(c[0]), "+f"(c[1]), "+f"(c[2]), "+f"(c[3])
        : "r"(a[0]), "r"(a[1]), "r"(a[2]), "r"(a[3]), "r"(b0), "r"(b1));
}
#define LDMX4(r, addr) \
    asm volatile("ldmatrix.sync.aligned.m8n8.x4.shared.b16 {%0,%1,%2,%3}, [%4];" \
        : "=r"((r)[0]), "=r"((r)[1]), "=r"((r)[2]), "=r"((r)[3]) : "r"(addr))
#define CP16(dst, src, sz) \
    asm volatile("cp.async.cg.shared.global [%0], [%1], 16, %2;" :: "r"(dst), "l"(src), "r"(sz))
#define CP_COMMIT() asm volatile("cp.async.commit_group;" ::: "memory")
#define CP_WAIT0() asm volatile("cp.async.wait_group 0;" ::: "memory")
#define CP_WAIT1() asm volatile("cp.async.wait_group 1;" ::: "memory")
#define CP_WAIT2() asm volatile("cp.async.wait_group 2;" ::: "memory")

// ================= gemm1: AB = 3-term split GEMM, tile 128x128, BK=64, 2-stage =================
// segment order: Ahi*Bhi, Ahi*Blo, Alo*Bhi  (A_hi chunks reused back-to-back -> L2 hits)
__global__ __launch_bounds__(256, 2) void gemm_ab_kernel(
    const __nv_bfloat16* __restrict__ Ahi, const __nv_bfloat16* __restrict__ Alo,
    const __nv_bfloat16* __restrict__ Bhi, const __nv_bfloat16* __restrict__ Blo,
    float* __restrict__ C, int M, int Ktot, int NT) {
    extern __shared__ __nv_bfloat16 sm1[];
    // stage s: A at s*36864 bytes, B at +18432
    int tid = threadIdx.x;
    int wid = tid >> 5, lane = tid & 31;
    int warp_m = wid & 3, warp_n = wid >> 2;
    int n0 = blockIdx.x * 128;
    int m0 = blockIdx.y * 128;

    float acc[2][8][4];
#pragma unroll
    for (int mi = 0; mi < 2; mi++)
#pragma unroll
        for (int ni = 0; ni < 8; ni++)
#pragma unroll
            for (int q = 0; q < 4; q++) acc[mi][ni][q] = 0.0f;

    const int cpseg = Ktot >> 6;
    const int nch = 3 * cpseg;
    uint32_t sbase = smem_u32(sm1);

#define LOAD1(i, buf) do { \
    int seg_ = (i) / cpseg; \
    int kb_ = ((i) - seg_ * cpseg) << 6; \
    const __nv_bfloat16* Ap_ = (seg_ == 2) ? Alo : Ahi; \
    const __nv_bfloat16* Bp_ = (seg_ == 1) ? Blo : Bhi; \
    uint32_t ab_ = sbase + (buf) * 36864; \
    _Pragma("unroll") \
    for (int q_ = 0; q_ < 4; q_++) { \
        int slot_ = tid + q_ * 256; \
        int row_ = slot_ >> 3, g_ = slot_ & 7; \
        int m_ = m0 + row_; \
        int ok_ = (m_ < M) ? 16 : 0; \
        int mc_ = (m_ < M) ? m_ : 0; \
        CP16(ab_ + row_ * 144 + g_ * 16, Ap_ + (size_t)mc_ * Ktot + kb_ + g_ * 8, ok_); \
        CP16(ab_ + 18432 + row_ * 144 + g_ * 16, \
             Bp_ + (size_t)(n0 + row_) * Ktot + kb_ + g_ * 8, 16); \
    } \
    CP_COMMIT(); \
} while (0)

    uint32_t aOff = (uint32_t)((warp_m * 32 + (lane & 15)) * 144 + (lane >> 4) * 16);
    uint32_t bOff = (uint32_t)((warp_n * 64 + ((lane >> 4) << 3) + (lane & 7)) * 144 +
                               ((lane >> 3) & 1) * 16) + 18432u;

    LOAD1(0, 0);
    for (int i = 0; i < nch; i++) {
        int buf = i & 1;
        if (i + 1 < nch) { LOAD1(i + 1, (i + 1) & 1); CP_WAIT1(); }
        else CP_WAIT0();
        __syncthreads();
        uint32_t ab = sbase + buf * 36864;
#pragma unroll
        for (int kk = 0; kk < 64; kk += 16) {
            uint32_t a[2][4];
#pragma unroll
            for (int mi = 0; mi < 2; mi++)
                LDMX4(a[mi], ab + aOff + (uint32_t)(mi * 16 * 144 + kk * 2));
            uint32_t bb[4][4];
#pragma unroll
            for (int p = 0; p < 4; p++)
                LDMX4(bb[p], ab + bOff + (uint32_t)(p * 16 * 144 + kk * 2));
#pragma unroll
            for (int ni = 0; ni < 8; ni++) {
                int p = ni >> 1, h = (ni & 1) * 2;
                mma16816(acc[0][ni], a[0], bb[p][h], bb[p][h + 1]);
                mma16816(acc[1][ni], a[1], bb[p][h], bb[p][h + 1]);
            }
        }
        __syncthreads();
    }
#undef LOAD1

#pragma unroll
    for (int mi = 0; mi < 2; mi++) {
#pragma unroll
        for (int ni = 0; ni < 8; ni++) {
            int row = m0 + warp_m * 32 + mi * 16 + (lane >> 2);
            int col = n0 + warp_n * 64 + ni * 8 + (lane & 3) * 2;
            if (row < M)
                *(float2*)&C[(size_t)row * NT + col] = make_float2(acc[mi][ni][0], acc[mi][ni][1]);
            if (row + 8 < M)
                *(float2*)&C[(size_t)(row + 8) * NT + col] = make_float2(acc[mi][ni][2], acc[mi][ni][3]);
        }
    }
}

// ================= gemm2 fused: Y-fold + residual + bias + bf16 split =================
// tile 128x384 (all 3 output blocks in CTA), 512 threads, 16 warps (4m x 4n),
// warp covers interleaved cols {wn*32+t*8 + b*128}. BK=32, 3-stage cp.async.
__global__ __launch_bounds__(512, 1) void gemm_post_kernel(
    const __nv_bfloat16* __restrict__ Bhi, const __nv_bfloat16* __restrict__ Blo,
    const float* __restrict__ hcur, const float* __restrict__ bpost,
    float* __restrict__ hnext, int M) {
    extern __shared__ __nv_bfloat16 sm2[];
    // stage s (40960 B): A(128x80B) at s*40960, B(384x80B) at +10240
    const int Ktot = 640;
    int tid = threadIdx.x;
    int wid = tid >> 5, lane = tid & 31;
    int warp_m = wid & 3, warp_n = (wid >> 2) & 3;
    int m0 = blockIdx.x * 128;

    float acc[2][12][4];
#pragma unroll
    for (int mi = 0; mi < 2; mi++)
#pragma unroll
        for (int ni = 0; ni < 12; ni++)
#pragma unroll
            for (int q = 0; q < 4; q++) acc[mi][ni][q] = 0.0f;

    const int cpseg = Ktot >> 5;   // 20
    const int nch = 3 * cpseg;     // 60
    uint32_t sbase = smem_u32(sm2);
    const __nv_bfloat16* Ahi = g_HAhi;
    const __nv_bfloat16* Alo = g_HAlo;

#define LOAD2(i, buf) do { \
    int seg_ = (i) / cpseg; \
    int kb_ = ((i) - seg_ * cpseg) << 5; \
    const __nv_bfloat16* Ap_ = (seg_ == 2) ? Alo : Ahi; \
    const __nv_bfloat16* Bp_ = (seg_ == 1) ? Blo : Bhi; \
    uint32_t ab_ = sbase + (buf) * 40960; \
    _Pragma("unroll") \
    for (int q_ = 0; q_ < 4; q_++) { \
        int slot_ = tid + q_ * 512; \
        if (slot_ < 512) { \
            int row_ = slot_ >> 2, g_ = slot_ & 3; \
            int m_ = m0 + row_; \
            int ok_ = (m_ < M) ? 16 : 0; \
            int mc_ = (m_ < M) ? m_ : 0; \
            CP16(ab_ + row_ * 80 + g_ * 16, Ap_ + (size_t)mc_ * Ktot + kb_ + g_ * 8, ok_); \
        } else { \
            int s2_ = slot_ - 512; \
            int row_ = s2_ >> 2, g_ = s2_ & 3; \
            CP16(ab_ + 10240 + row_ * 80 + g_ * 16, \
                 Bp_ + (size_t)row_ * Ktot + kb_ + g_ * 8, 16); \
        } \
    } \
    CP_COMMIT(); \
} while (0)

    uint32_t aOff = (uint32_t)((warp_m * 32 + (lane & 15)) * 80 + (lane >> 4) * 16);
    uint32_t bOff = (uint32_t)((warp_n * 32 + ((lane >> 4) << 3) + (lane & 7)) * 80 +
                               ((lane >> 3) & 1) * 16) + 10240u;

    LOAD2(0, 0);
    LOAD2(1, 1);
    for (int i = 0; i < nch; i++) {
        int buf = i - (i / 3) * 3;
        if (i + 2 < nch) {
            int nb = (i + 2) - ((i + 2) / 3) * 3;
            LOAD2(i + 2, nb);
            CP_WAIT2();
        } else if (i + 1 < nch) {
            CP_WAIT1();
        } else {
            CP_WAIT0();
        }
        __syncthreads();
        uint32_t ab = sbase + buf * 40960;
#pragma unroll
        for (int kk = 0; kk < 32; kk += 16) {
            uint32_t a[2][4];
#pragma unroll
            for (int mi = 0; mi < 2; mi++)
                LDMX4(a[mi], ab + aOff + (uint32_t)(mi * 16 * 80 + kk * 2));
#pragma unroll
            for (int b = 0; b < 3; b++) {
                uint32_t bb[2][4];
#pragma unroll
                for (int p = 0; p < 2; p++)
                    LDMX4(bb[p], ab + bOff + (uint32_t)((b * 128 + p * 16) * 80 + kk * 2));
#pragma unroll
                for (int t = 0; t < 4; t++) {
                    int p = t >> 1, h = (t & 1) * 2;
                    mma16816(acc[0][b * 4 + t], a[0], bb[p][h], bb[p][h + 1]);
                    mma16816(acc[1][b * 4 + t], a[1], bb[p][h], bb[p][h + 1]);
                }
            }
        }
        __syncthreads();
    }
#undef LOAD2

    // fused epilogue: hnext = y0 + amp*y1 + att*y2 + bpost + hcur; bf16 hi/lo split
#pragma unroll
    for (int mi = 0; mi < 2; mi++) {
        int r0 = m0 + warp_m * 32 + mi * 16 + (lane >> 2);
        int r1 = r0 + 8;
        float amp0 = 0.f, att0 = 0.f, amp1 = 0.f, att1 = 0.f;
        if (r0 < M) { amp0 = g_amp[r0]; att0 = g_att[r0]; }
        if (r1 < M) { amp1 = g_amp[r1]; att1 = g_att[r1]; }
#pragma unroll
        for (int t = 0; t < 4; t++) {
            int c = warp_n * 32 + t * 8 + (lane & 3) * 2;
            float bp0 = bpost[c], bp1 = bpost[c + 1];
            float* y0 = acc[mi][t];
            float* y1 = acc[mi][4 + t];
            float* y2 = acc[mi][8 + t];
            if (r0 < M) {
                int o = r0 * HH + c;
                float v0 = y0[0] + amp0 * y1[0] + att0 * y2[0] + bp0 + hcur[o];
                float v1 = y0[1] + amp0 * y1[1] + att0 * y2[1] + bp1 + hcur[o + 1];
                *(float2*)&hnext[o] = make_float2(v0, v1);
                __nv_bfloat16 h0, l0, h1, l1;
                split_bf(v0, h0, l0); split_bf(v1, h1, l1);
                __nv_bfloat162 hp = __halves2bfloat162(h0, h1);
                __nv_bfloat162 lp = __halves2bfloat162(l0, l1);
                *(uint32_t*)&g_hhi[o] = *(uint32_t*)&hp;
                *(uint32_t*)&g_hlo[o] = *(uint32_t*)&lp;
            }
            if (r1 < M) {
                int o = r1 * HH + c;
                float v0 = y0[2] + amp1 * y1[2] + att1 * y2[2] + bp0 + hcur[o];
                float v1 = y0[3] + amp1 * y1[3] + att1 * y2[3] + bp1 + hcur[o + 1];
                *(float2*)&hnext[o] = make_float2(v0, v1);
                __nv_bfloat16 h0, l0, h1, l1;
                split_bf(v0, h0, l0); split_bf(v1, h1, l1);
                __nv_bfloat162 hp = __halves2bfloat162(h0, h1);
                __nv_bfloat162 lp = __halves2bfloat162(l0, l1);
                *(uint32_t*)&g_hhi[o] = *(uint32_t*)&hp;
                *(uint32_t*)&g_hlo[o] = *(uint32_t*)&lp;
            }
        }
    }
}

// ================= fp32 tiled GEMM for small head GEMMs =================
__global__ void gemm_kernel(const float* __restrict__ A, const float* __restrict__ B,
                            float* __restrict__ C, const float* __restrict__ bias,
                            int M, int N, int K, int ldc, int relu) {
    __shared__ float As[16][64];
    __shared__ float Bs[16][64];
    int tid = threadIdx.x;
    int tx = tid & 15, ty = tid >> 4;
    int row0 = blockIdx.y * 64, col0 = blockIdx.x * 64;
    float acc[4][4];
#pragma unroll
    for (int i = 0; i < 4; i++)
#pragma unroll
        for (int j = 0; j < 4; j++) acc[i][j] = 0.0f;
    int ar = tid >> 2, ac = (tid & 3) * 4;
    int br = tid >> 4, bc = (tid & 15) * 4;
    int arow = row0 + ar;
    for (int k0 = 0; k0 < K; k0 += 16) {
        float4 a4 = make_float4(0, 0, 0, 0);
        if (arow < M) a4 = *(const float4*)&A[arow * K + k0 + ac];
        As[ac + 0][ar] = a4.x; As[ac + 1][ar] = a4.y; As[ac + 2][ar] = a4.z; As[ac + 3][ar] = a4.w;
        *(float4*)&Bs[br][bc] = *(const float4*)&B[(k0 + br) * N + col0 + bc];
        __syncthreads();
#pragma unroll
        for (int k = 0; k < 16; k++) {
            float4 av = *(const float4*)&As[k][ty * 4];
            float4 bv = *(const float4*)&Bs[k][tx * 4];
            acc[0][0] += av.x * bv.x; acc[0][1] += av.x * bv.y; acc[0][2] += av.x * bv.z; acc[0][3] += av.x * bv.w;
            acc[1][0] += av.y * bv.x; acc[1][1] += av.y * bv.y; acc[1][2] += av.y * bv.z; acc[1][3] += av.y * bv.w;
            acc[2][0] += av.z * bv.x; acc[2][1] += av.z * bv.y; acc[2][2] += av.z * bv.z; acc[2][3] += av.z * bv.w;
            acc[3][0] += av.w * bv.x; acc[3][1] += av.w * bv.y; acc[3][2] += av.w * bv.z; acc[3][3] += av.w * bv.w;
        }
        __syncthreads();
    }
#pragma unroll
    for (int i = 0; i < 4; i++) {
        int r = row0 + ty * 4 + i;
        if (r >= M) continue;
#pragma unroll
        for (int j = 0; j < 4; j++) {
            int col = col0 + tx * 4 + j;
            float v = acc[i][j];
            if (bias) v += bias[col];
            if (relu) v = fmaxf(v, 0.0f);
            C[r * ldc + col] = v;
        }
    }
}

static void launch_gemm(const float* A, const float* B, float* C, const float* bias,
                        int M, int N, int K, int ldc, int relu) {
    dim3 grid(N / 64, (M + 63) / 64);
    gemm_kernel<<<grid, 256>>>(A, B, C, bias, M, N, K, ldc, relu);
}

// ================= host =================
extern "C" void kernel_launch(void* const* d_in, const int* in_sizes, int n_in,
                              void* d_out, int out_size) {
    const int *node_feat = 0, *edge_feat = 0, *srcp = 0, *dstp = 0;
    const float *aemb_f = 0, *bemb_f = 0, *wpre_f = 0, *bpre_f = 0, *wpost_f = 0, *bpost_f = 0;
    const float *wout3 = 0, *bout3 = 0;
    const float *aemb = 0, *bemb = 0, *wpre = 0, *bpre = 0, *wpost = 0, *bpost = 0;
    const float *w1 = 0, *b1 = 0, *w2 = 0, *b2 = 0;
    int c400k = 0, c18432 = 0, c1920 = 0, c245760 = 0, c640 = 0, c1064960 = 0, c128 = 0;
    for (int i = 0; i < n_in; i++) {
        int sz = in_sizes[i];
        void* p = d_in[i];
        switch (sz) {
            case 450000: node_feat = (const int*)p; break;
            case 1200000: edge_feat = (const int*)p; break;
            case 400000: if (c400k++ == 0) srcp = (const int*)p; else dstp = (const int*)p; break;
            case 50000: break;
            case 18432: if (c18432++ == 0) aemb_f = (const float*)p; else aemb = (const float*)p; break;
            case 1920: if (c1920++ == 0) bemb_f = (const float*)p; else bemb = (const float*)p; break;
            case 245760: if (c245760++ == 0) wpre_f = (const float*)p; else wpre = (const float*)p; break;
            case 640: {
                int k = c640++;
                if (k == 0) bpre_f = (const float*)p;
                else if (k == 1) bpost_f = (const float*)p;
                else if (k == 2) bpre = (const float*)p;
                else bpost = (const float*)p;
            } break;
            case 1064960: if (c1064960++ == 0) wpost_f = (const float*)p; else wpost = (const float*)p; break;
            case 98304: wout3 = (const float*)p; break;
            case 256: bout3 = (const float*)p; break;
            case 81920: w1 = (const float*)p; break;
            case 128: if (c128++ == 0) b1 = (const float*)p; else b2 = (const float*)p; break;
            case 16384: w2 = (const float*)p; break;
            default: break;
        }
    }

    float *AB, *h0b, *h1b, *combo, *Ctab, *R3, *XB, *H1;
    __nv_bfloat16 *WsdHi, *WsdLo, *WbigHi, *WbigLo, *hhi, *hlo;
    int *deg, *cursor;
    cudaGetSymbolAddress((void**)&AB, g_AB);
    cudaGetSymbolAddress((void**)&h0b, g_hbuf0);
    cudaGetSymbolAddress((void**)&h1b, g_hbuf1);
    cudaGetSymbolAddress((void**)&combo, g_combo);
    cudaGetSymbolAddress((void**)&Ctab, g_Ctab);
    cudaGetSymbolAddress((void**)&R3, g_R3);
    cudaGetSymbolAddress((void**)&XB, g_XB);
    cudaGetSymbolAddress((void**)&H1, g_H1);
    cudaGetSymbolAddress((void**)&WsdHi, g_WsdHi);
    cudaGetSymbolAddress((void**)&WsdLo, g_WsdLo);
    cudaGetSymbolAddress((void**)&WbigHi, g_WbigHi);
    cudaGetSymbolAddress((void**)&WbigLo, g_WbigLo);
    cudaGetSymbolAddress((void**)&hhi, g_hhi);
    cudaGetSymbolAddress((void**)&hlo, g_hlo);
    cudaGetSymbolAddress((void**)&deg, g_deg);
    cudaGetSymbolAddress((void**)&cursor, g_cursor);

    cudaFuncSetAttribute(gemm_ab_kernel, cudaFuncAttributeMaxDynamicSharedMemorySize, 73728);
    cudaFuncSetAttribute(gemm_post_kernel, cudaFuncAttributeMaxDynamicSharedMemorySize, 122880);

    cudaMemsetAsync(deg, 0, NN * sizeof(int));
    cudaMemsetAsync(cursor, 0, NN * sizeof(int));
    count_kernel<<<(EE + 255) / 256, 256>>>(dstp);
    scan_kernel<<<1, 1024>>>();
    scalars_kernel<<<(NN + 255) / 256, 256>>>();
    fill_kernel<<<(EE + 255) / 256, 256>>>(srcp, dstp, edge_feat);

    const float* bembs[2] = { bemb_f, bemb };
    const float* aembs[2] = { aemb_f, aemb };
    const float* wpres[2] = { wpre_f, wpre };
    const float* bpres[2] = { bpre_f, bpre };
    const float* wposts[2] = { wpost_f, wpost };
    const float* bposts[2] = { bpost_f, bpost };
    for (int br = 0; br < 2; br++) {
        combo_kernel<<<125, 128>>>(bembs[br], combo + br * 125 * HH);
        ctab_kernel<<<dim3(125, LL), 128>>>(combo + br * 125 * HH, wpres[br], bpres[br],
                                            Ctab + br * LL * 125 * HH);
        pack_wsd_kernel<<<(LL * 256 * 128 + 255) / 256, 256>>>(wpres[br],
            WsdHi + br * LL * 256 * 128, WsdLo + br * LL * 256 * 128);
        pack_wbig_kernel<<<(LL * 384 * 640 + 255) / 256, 256>>>(wposts[br],
            WbigHi + (size_t)br * LL * 384 * 640, WbigLo + (size_t)br * LL * 384 * 640);
    }

    const int MT = (NN + 127) / 128;   // 391

    for (int br = 0; br < 2; br++) {
        embed_kernel<<<NN, 128>>>(aembs[br], node_feat, h0b);
        float* hcur = h0b;
        float* hnext = h1b;
        for (int l = 0; l < LL; l++) {
            gemm_ab_kernel<<<dim3(2, MT), 256, 73728>>>(
                hhi, hlo,
                WsdHi + br * LL * 256 * 128 + l * 256 * 128,
                WsdLo + br * LL * 256 * 128 + l * 256 * 128,
                AB, NN, 128, 256);
            aggregate_kernel<<<(NN + 7) / 8, 256>>>(Ctab + (br * LL + l) * 125 * HH);
            gemm_post_kernel<<<MT, 512, 122880>>>(
                WbigHi + (size_t)br * LL * 384 * 640 + (size_t)l * 384 * 640,
                WbigLo + (size_t)br * LL * 384 * 640 + (size_t)l * 384 * 640,
                hcur, bposts[br] + l * 128, hnext, NN);
            float* tmp = hcur; hcur = hnext; hnext = tmp;
        }
        if (br == 0) {
            readout_kernel<<<GG, 128>>>(hcur, R3, 384);
            launch_gemm(R3, wout3, XB + 384, bout3, GG, 256, 384, 640, 0);
        } else {
            readout_kernel<<<GG, 128>>>(hcur, XB, 640);
        }
    }

    launch_gemm(XB, w1, H1, b1, GG, 128, 640, 128, 1);
    launch_gemm(H1, w2, (float*)d_out, b2, GG, 128, 128, 128, 0);
    (void)out_size;
}